// round 3
// baseline (speedup 1.0000x reference)
#include <cuda_runtime.h>
#include <cstdint>
#include <cfloat>

#define BATCH 4
#define SEQ   2048
#define DMODEL 128
#define DLOW  16
#define NEGV  (-1e9f)
#define SCALE 0.25f

// ---- scratch (static __device__, no allocations) ----
__device__ float g_S[BATCH * SEQ * SEQ];          // 64 MB corrected scores
__device__ float g_qlow[BATCH * SEQ * DLOW];
__device__ float g_klowT[BATCH * DLOW * SEQ];     // transposed for coalesced GEMM loads
__device__ float g_c[BATCH * SEQ];                // per-position correction score
__device__ float g_w[BATCH * SEQ];                // exp(-colmax)/colZ

// ============================================================
// K1: projections. One block (64 threads) per (b, position).
// warp-halves compute q_low, k_low, q_high, k_high; thread 0 reduces c.
// ============================================================
__global__ void proj_kernel(const float* __restrict__ q, const float* __restrict__ k,
                            const float* __restrict__ Wql, const float* __restrict__ bql,
                            const float* __restrict__ Wkl, const float* __restrict__ bkl,
                            const float* __restrict__ Wqh, const float* __restrict__ bqh,
                            const float* __restrict__ Wkh, const float* __restrict__ bkh)
{
    int p = blockIdx.x;                       // 0..BATCH*SEQ-1
    int b = p >> 11, i = p & (SEQ - 1);
    __shared__ float qs[DMODEL], ks[DMODEL];
    __shared__ float qh[DLOW], kh[DLOW];
    int t = threadIdx.x;                      // 0..63
    {
        float2 qv = *(const float2*)&q[p * DMODEL + t * 2];
        qs[t * 2] = qv.x; qs[t * 2 + 1] = qv.y;
        float2 kv = *(const float2*)&k[p * DMODEL + t * 2];
        ks[t * 2] = kv.x; ks[t * 2 + 1] = kv.y;
    }
    __syncthreads();
    int j = t & 15;
    int which = t >> 4;                       // 0:qlow 1:klow 2:qhigh 3:khigh
    const float* W; const float* bias; const float* src;
    if (which == 0)      { W = Wql; bias = bql; src = qs; }
    else if (which == 1) { W = Wkl; bias = bkl; src = ks; }
    else if (which == 2) { W = Wqh; bias = bqh; src = qs; }
    else                 { W = Wkh; bias = bkh; src = ks; }
    float acc = bias[j];
    #pragma unroll 16
    for (int d0 = 0; d0 < DMODEL; d0++)
        acc = fmaf(src[d0], W[d0 * DLOW + j], acc);
    if (which == 0)      g_qlow[p * DLOW + j] = acc;
    else if (which == 1) g_klowT[(b * DLOW + j) * SEQ + i] = acc;
    else if (which == 2) qh[j] = acc;
    else                 kh[j] = acc;
    __syncthreads();
    if (t == 0) {
        float c = 0.f;
        #pragma unroll
        for (int jj = 0; jj < DLOW; jj++) c = fmaf(qh[jj], kh[jj], c);
        g_c[p] = c * SCALE;
    }
}

// ============================================================
// K2a: masked low-rank scores S = 0.25 * Q_low @ K_low^T  (+NEG at vl[b,k]==q)
// block: 64q x 128k tile, 256 threads, thread = 8x4.
// ============================================================
__global__ void scores_kernel(const int* __restrict__ valid_lens)
{
    int b  = blockIdx.z;
    int q0 = blockIdx.y * 64;
    int k0 = blockIdx.x * 128;
    __shared__ float qT[DLOW][64];     // [j][m]
    __shared__ float kS[DLOW][128];    // [j][n]
    int t = threadIdx.x;
    {
        int row = t >> 2, j0 = (t & 3) * 4;
        const float4 v = *(const float4*)&g_qlow[(b * SEQ + q0 + row) * DLOW + j0];
        qT[j0 + 0][row] = v.x; qT[j0 + 1][row] = v.y;
        qT[j0 + 2][row] = v.z; qT[j0 + 3][row] = v.w;
    }
    {
        int row = t >> 5, c0 = (t & 31) * 4;
        #pragma unroll
        for (int r = 0; r < DLOW; r += 8)
            *(float4*)&kS[row + r][c0] =
                *(const float4*)&g_klowT[(b * DLOW + row + r) * SEQ + k0 + c0];
    }
    __syncthreads();
    int tx = t & 31, ty = t >> 5;
    int m0 = ty * 8, n0 = tx * 4;
    float acc[8][4];
    #pragma unroll
    for (int i = 0; i < 8; i++)
        #pragma unroll
        for (int jj = 0; jj < 4; jj++) acc[i][jj] = 0.f;
    #pragma unroll
    for (int j = 0; j < DLOW; j++) {
        float a[8];
        *(float4*)&a[0] = *(const float4*)&qT[j][m0];
        *(float4*)&a[4] = *(const float4*)&qT[j][m0 + 4];
        float4 bv = *(const float4*)&kS[j][n0];
        #pragma unroll
        for (int i = 0; i < 8; i++) {
            acc[i][0] = fmaf(a[i], bv.x, acc[i][0]);
            acc[i][1] = fmaf(a[i], bv.y, acc[i][1]);
            acc[i][2] = fmaf(a[i], bv.z, acc[i][2]);
            acc[i][3] = fmaf(a[i], bv.w, acc[i][3]);
        }
    }
    int vl[4];
    #pragma unroll
    for (int jj = 0; jj < 4; jj++) {
        int v = valid_lens[b * SEQ + k0 + n0 + jj];
        vl[jj] = min(max(v, 0), SEQ - 1);
    }
    #pragma unroll
    for (int i = 0; i < 8; i++) {
        int qrow = q0 + m0 + i;
        float4 o; float* po = (float*)&o;
        #pragma unroll
        for (int jj = 0; jj < 4; jj++) {
            float v = acc[i][jj] * SCALE;
            if (vl[jj] == qrow) v += NEGV;
            po[jj] = v;
        }
        *(float4*)&g_S[(b * SEQ + qrow) * SEQ + k0 + n0] = o;
    }
}

// ============================================================
// K2b: per-row top-8 (iterative argmax, lowest-index tie-break like jax)
// then scatter corrected values c[b, idx] into S. One block per row.
// ============================================================
__global__ void topk_kernel()
{
    int b = blockIdx.y, qrow = blockIdx.x;
    float* Srow = &g_S[(b * SEQ + qrow) * SEQ];
    __shared__ float sv[SEQ];
    __shared__ float wv[8];
    __shared__ int   wi[8];
    __shared__ int   topk[8];
    int t = threadIdx.x;                       // 0..255
    #pragma unroll
    for (int r = 0; r < 2; r++) {
        int idx = (t + r * 256) * 4;
        *(float4*)&sv[idx] = *(const float4*)&Srow[idx];
    }
    __syncthreads();
    int lane = t & 31, w = t >> 5;
    for (int iter = 0; iter < 8; iter++) {
        float bv = -FLT_MAX; int bi = SEQ;
        int base = t * 8;                      // contiguous chunk -> stable ties
        #pragma unroll
        for (int jj = 0; jj < 8; jj++) {
            float v = sv[base + jj];
            if (v > bv) { bv = v; bi = base + jj; }
        }
        #pragma unroll
        for (int off = 16; off > 0; off >>= 1) {
            float ov = __shfl_down_sync(0xffffffffu, bv, off);
            int   oi = __shfl_down_sync(0xffffffffu, bi, off);
            if (ov > bv || (ov == bv && oi < bi)) { bv = ov; bi = oi; }
        }
        if (lane == 0) { wv[w] = bv; wi[w] = bi; }
        __syncthreads();
        if (t == 0) {
            float fv = wv[0]; int fi = wi[0];
            #pragma unroll
            for (int x = 1; x < 8; x++)
                if (wv[x] > fv || (wv[x] == fv && wi[x] < fi)) { fv = wv[x]; fi = wi[x]; }
            topk[iter] = fi;
            sv[fi] = -FLT_MAX;
        }
        __syncthreads();
    }
    if (t < 8) {
        int kk = topk[t];
        Srow[kk] = g_c[b * SEQ + kk];          // .set semantics (replace)
    }
}

// ============================================================
// K3: column-wise (axis=q) online softmax stats -> w[b,k] = exp(-m)/Z
// block: 128 columns x 4-way q split, coalesced along k.
// ============================================================
__global__ void colstats_kernel()
{
    int b = blockIdx.y;
    int kcol = blockIdx.x * 128 + threadIdx.x;
    int y = threadIdx.y;
    const float* base = &g_S[b * SEQ * SEQ + kcol];
    float m = -FLT_MAX, sum = 0.f;
    for (int qr = y; qr < SEQ; qr += 4) {
        float v = base[qr * SEQ];
        if (v > m) { sum = sum * __expf(m - v) + 1.f; m = v; }
        else       sum += __expf(v - m);
    }
    __shared__ float sm[4][128], ss[4][128];
    sm[y][threadIdx.x] = m; ss[y][threadIdx.x] = sum;
    __syncthreads();
    if (y == 0) {
        #pragma unroll
        for (int x = 1; x < 4; x++) {
            float m2 = sm[x][threadIdx.x], s2 = ss[x][threadIdx.x];
            if (m2 > m) { sum = sum * __expf(m - m2) + s2; m = m2; }
            else        sum += s2 * __expf(m2 - m);
        }
        g_w[b * SEQ + kcol] = __expf(-m) / sum;
    }
}

// ============================================================
// K4: out[q,:] = sum_k exp(S[q,k]) * (V[k,:] * w[k])
// 64q x 128d tile per block, BK=32, 256 threads, thread = 8q x 4d.
// q paired into f32x2 accumulators driven by fma.rn.f32x2 (2 FMA/instr).
// ============================================================
__global__ void out_gemm_kernel(const float* __restrict__ V, float* __restrict__ out)
{
    int b  = blockIdx.y;
    int q0 = blockIdx.x * 64;
    __shared__ float Ps[32][66];       // [kk][m], stride 66: 8B aligned, low conflict
    __shared__ float Vsh[32][128];     // [kk][d], pre-scaled by w[k]
    int t = threadIdx.x;
    int tx = t & 31, ty = t >> 5;
    int m0 = ty * 8, n0 = tx * 4;

    unsigned long long acc[4][4];
    #pragma unroll
    for (int pi = 0; pi < 4; pi++)
        #pragma unroll
        for (int jj = 0; jj < 4; jj++) acc[pi][jj] = 0ull;

    const float* Sbase = &g_S[(b * SEQ + q0) * SEQ];
    const float* Vbase = &V[b * SEQ * DMODEL];
    const float* wbase = &g_w[b * SEQ];

    for (int kt = 0; kt < SEQ; kt += 32) {
        {   // S tile 64x32 -> exp -> transposed smem
            int q_l = t >> 3;
            int kg  = (t & 7) * 4;
            #pragma unroll
            for (int pass = 0; pass < 2; pass++) {
                int qq = q_l + pass * 32;
                float4 sv = *(const float4*)&Sbase[qq * SEQ + kt + kg];
                Ps[kg + 0][qq] = __expf(sv.x);
                Ps[kg + 1][qq] = __expf(sv.y);
                Ps[kg + 2][qq] = __expf(sv.z);
                Ps[kg + 3][qq] = __expf(sv.w);
            }
        }
        {   // V tile 32x128, scaled by w
            int row = t >> 5;
            int c0  = (t & 31) * 4;
            #pragma unroll
            for (int pass = 0; pass < 4; pass++) {
                int rr = row + pass * 8;
                float wk = wbase[kt + rr];
                float4 vv = *(const float4*)&Vbase[(kt + rr) * DMODEL + c0];
                vv.x *= wk; vv.y *= wk; vv.z *= wk; vv.w *= wk;
                *(float4*)&Vsh[rr][c0] = vv;
            }
        }
        __syncthreads();
        #pragma unroll
        for (int kk = 0; kk < 32; kk++) {
            unsigned long long ap[4];
            #pragma unroll
            for (int pi = 0; pi < 4; pi++)
                ap[pi] = *(const unsigned long long*)&Ps[kk][m0 + pi * 2];
            float4 bv = *(const float4*)&Vsh[kk][n0];
            unsigned long long bd[4];
            asm("mov.b64 %0, {%1, %1};" : "=l"(bd[0]) : "r"(__float_as_uint(bv.x)));
            asm("mov.b64 %0, {%1, %1};" : "=l"(bd[1]) : "r"(__float_as_uint(bv.y)));
            asm("mov.b64 %0, {%1, %1};" : "=l"(bd[2]) : "r"(__float_as_uint(bv.z)));
            asm("mov.b64 %0, {%1, %1};" : "=l"(bd[3]) : "r"(__float_as_uint(bv.w)));
            #pragma unroll
            for (int pi = 0; pi < 4; pi++)
                #pragma unroll
                for (int jj = 0; jj < 4; jj++)
                    asm("fma.rn.f32x2 %0, %1, %2, %0;"
                        : "+l"(acc[pi][jj]) : "l"(ap[pi]), "l"(bd[jj]));
        }
        __syncthreads();
    }
    #pragma unroll
    for (int pi = 0; pi < 4; pi++) {
        float4 lo4, hi4;
        float* lo = (float*)&lo4; float* hi = (float*)&hi4;
        #pragma unroll
        for (int jj = 0; jj < 4; jj++) {
            unsigned int l, h;
            asm("mov.b64 {%0, %1}, %2;" : "=r"(l), "=r"(h) : "l"(acc[pi][jj]));
            lo[jj] = __uint_as_float(l);
            hi[jj] = __uint_as_float(h);
        }
        int qa = q0 + m0 + pi * 2;
        *(float4*)&out[(b * SEQ + qa) * DMODEL + n0]     = lo4;
        *(float4*)&out[(b * SEQ + qa + 1) * DMODEL + n0] = hi4;
    }
}

// ============================================================
extern "C" void kernel_launch(void* const* d_in, const int* in_sizes, int n_in,
                              void* d_out, int out_size)
{
    const float* queries = (const float*)d_in[0];
    const float* keys    = (const float*)d_in[1];
    const float* values  = (const float*)d_in[2];
    const int*   vlens   = (const int*)  d_in[3];
    const float* Wql     = (const float*)d_in[4];
    const float* bql     = (const float*)d_in[5];
    const float* Wkl     = (const float*)d_in[6];
    const float* bkl     = (const float*)d_in[7];
    const float* Wqh     = (const float*)d_in[8];
    const float* bqh     = (const float*)d_in[9];
    const float* Wkh     = (const float*)d_in[10];
    const float* bkh     = (const float*)d_in[11];
    float* out = (float*)d_out;

    proj_kernel<<<BATCH * SEQ, 64>>>(queries, keys, Wql, bql, Wkl, bkl,
                                     Wqh, bqh, Wkh, bkh);
    scores_kernel<<<dim3(SEQ / 128, SEQ / 64, BATCH), 256>>>(vlens);
    topk_kernel<<<dim3(SEQ, BATCH), 256>>>();
    colstats_kernel<<<dim3(SEQ / 128, BATCH), dim3(128, 4)>>>();
    out_gemm_kernel<<<dim3(SEQ / 64, BATCH), 256>>>(values, out);
}

// round 4
// speedup vs baseline: 1.1219x; 1.1219x over previous
#include <cuda_runtime.h>
#include <cstdint>
#include <cfloat>

#define BATCH 4
#define SEQ   2048
#define DMODEL 128
#define DLOW  16
#define NEGV  (-1e9f)
#define SCALE 0.25f
#define QSEG  8

// ---- scratch (static __device__, no allocations) ----
__device__ float g_S[BATCH * SEQ * SEQ];          // 64 MB: exp(corrected scores)
__device__ float g_qlow[BATCH * SEQ * DLOW];
__device__ float g_klowT[BATCH * DLOW * SEQ];     // transposed for coalesced GEMM loads
__device__ float g_c[BATCH * SEQ];                // exp(correction score)
__device__ float g_w[BATCH * SEQ];                // 1 / column Z
__device__ float g_part[QSEG][BATCH * SEQ];       // column-sum partials

// ============================================================
// K1: projections. One block (64 threads) per (b, position).
// warp-halves compute q_low, k_low, q_high, k_high; thread 0 reduces c,
// stores exp(c * scale).
// ============================================================
__global__ void proj_kernel(const float* __restrict__ q, const float* __restrict__ k,
                            const float* __restrict__ Wql, const float* __restrict__ bql,
                            const float* __restrict__ Wkl, const float* __restrict__ bkl,
                            const float* __restrict__ Wqh, const float* __restrict__ bqh,
                            const float* __restrict__ Wkh, const float* __restrict__ bkh)
{
    int p = blockIdx.x;                       // 0..BATCH*SEQ-1
    int b = p >> 11, i = p & (SEQ - 1);
    __shared__ float qs[DMODEL], ks[DMODEL];
    __shared__ float qh[DLOW], kh[DLOW];
    int t = threadIdx.x;                      // 0..63
    {
        float2 qv = *(const float2*)&q[p * DMODEL + t * 2];
        qs[t * 2] = qv.x; qs[t * 2 + 1] = qv.y;
        float2 kv = *(const float2*)&k[p * DMODEL + t * 2];
        ks[t * 2] = kv.x; ks[t * 2 + 1] = kv.y;
    }
    __syncthreads();
    int j = t & 15;
    int which = t >> 4;                       // 0:qlow 1:klow 2:qhigh 3:khigh
    const float* W; const float* bias; const float* src;
    if (which == 0)      { W = Wql; bias = bql; src = qs; }
    else if (which == 1) { W = Wkl; bias = bkl; src = ks; }
    else if (which == 2) { W = Wqh; bias = bqh; src = qs; }
    else                 { W = Wkh; bias = bkh; src = ks; }
    float acc = bias[j];
    #pragma unroll 16
    for (int d0 = 0; d0 < DMODEL; d0++)
        acc = fmaf(src[d0], W[d0 * DLOW + j], acc);
    if (which == 0)      g_qlow[p * DLOW + j] = acc;
    else if (which == 1) g_klowT[(b * DLOW + j) * SEQ + i] = acc;
    else if (which == 2) qh[j] = acc;
    else                 kh[j] = acc;
    __syncthreads();
    if (t == 0) {
        float c = 0.f;
        #pragma unroll
        for (int jj = 0; jj < DLOW; jj++) c = fmaf(qh[jj], kh[jj], c);
        g_c[p] = __expf(c * SCALE);
    }
}

// ============================================================
// K2a: masked low-rank scores, stored as exp(score).
// S = exp(0.25 * Q_low @ K_low^T + mask)   (masked -> exp(-1e9) == 0)
// block: 64q x 128k tile, 256 threads, thread = 8x4.
// ============================================================
__global__ void scores_kernel(const int* __restrict__ valid_lens)
{
    int b  = blockIdx.z;
    int q0 = blockIdx.y * 64;
    int k0 = blockIdx.x * 128;
    __shared__ float qT[DLOW][64];     // [j][m]
    __shared__ float kS[DLOW][128];    // [j][n]
    int t = threadIdx.x;
    {
        int row = t >> 2, j0 = (t & 3) * 4;
        const float4 v = *(const float4*)&g_qlow[(b * SEQ + q0 + row) * DLOW + j0];
        qT[j0 + 0][row] = v.x; qT[j0 + 1][row] = v.y;
        qT[j0 + 2][row] = v.z; qT[j0 + 3][row] = v.w;
    }
    {
        int row = t >> 5, c0 = (t & 31) * 4;
        #pragma unroll
        for (int r = 0; r < DLOW; r += 8)
            *(float4*)&kS[row + r][c0] =
                *(const float4*)&g_klowT[(b * DLOW + row + r) * SEQ + k0 + c0];
    }
    __syncthreads();
    int tx = t & 31, ty = t >> 5;
    int m0 = ty * 8, n0 = tx * 4;
    float acc[8][4];
    #pragma unroll
    for (int i = 0; i < 8; i++)
        #pragma unroll
        for (int jj = 0; jj < 4; jj++) acc[i][jj] = 0.f;
    #pragma unroll
    for (int j = 0; j < DLOW; j++) {
        float a[8];
        *(float4*)&a[0] = *(const float4*)&qT[j][m0];
        *(float4*)&a[4] = *(const float4*)&qT[j][m0 + 4];
        float4 bv = *(const float4*)&kS[j][n0];
        #pragma unroll
        for (int i = 0; i < 8; i++) {
            acc[i][0] = fmaf(a[i], bv.x, acc[i][0]);
            acc[i][1] = fmaf(a[i], bv.y, acc[i][1]);
            acc[i][2] = fmaf(a[i], bv.z, acc[i][2]);
            acc[i][3] = fmaf(a[i], bv.w, acc[i][3]);
        }
    }
    int vl[4];
    #pragma unroll
    for (int jj = 0; jj < 4; jj++) {
        int v = valid_lens[b * SEQ + k0 + n0 + jj];
        vl[jj] = min(max(v, 0), SEQ - 1);
    }
    #pragma unroll
    for (int i = 0; i < 8; i++) {
        int qrow = q0 + m0 + i;
        float4 o; float* po = (float*)&o;
        #pragma unroll
        for (int jj = 0; jj < 4; jj++) {
            float v = acc[i][jj] * SCALE;
            if (vl[jj] == qrow) v += NEGV;
            po[jj] = __expf(v);
        }
        *(float4*)&g_S[(b * SEQ + qrow) * SEQ + k0 + n0] = o;
    }
}

// ============================================================
// K2b: per-row top-8 on exp'd scores (monotone => same indices),
// register-resident warp top-8 + single-warp 64-candidate merge.
// Scatters exp(c). Only 2 block-wide syncs.
// ============================================================
__global__ void topk_kernel()
{
    int b = blockIdx.y, qrow = blockIdx.x;
    float* Srow = &g_S[(b * SEQ + qrow) * SEQ];
    __shared__ float candV[64];
    __shared__ int   candI[64];
    __shared__ int   finalI[8];
    int t = threadIdx.x, lane = t & 31, w = t >> 5;
    int base = w * 256 + lane * 8;            // contiguous 8 per lane
    float v[8];
    *(float4*)&v[0] = *(const float4*)&Srow[base];
    *(float4*)&v[4] = *(const float4*)&Srow[base + 4];

    // per-warp top-8 (values desc, index asc tie-break), shuffle-only
    #pragma unroll
    for (int iter = 0; iter < 8; iter++) {
        float bv = -FLT_MAX; int bi = 0x7fffffff;
        #pragma unroll
        for (int jj = 0; jj < 8; jj++)
            if (v[jj] > bv) { bv = v[jj]; bi = base + jj; }
        #pragma unroll
        for (int off = 16; off > 0; off >>= 1) {
            float ov = __shfl_down_sync(0xffffffffu, bv, off);
            int   oi = __shfl_down_sync(0xffffffffu, bi, off);
            if (ov > bv || (ov == bv && oi < bi)) { bv = ov; bi = oi; }
        }
        bv = __shfl_sync(0xffffffffu, bv, 0);
        bi = __shfl_sync(0xffffffffu, bi, 0);
        if (lane == 0) { candV[w * 8 + iter] = bv; candI[w * 8 + iter] = bi; }
        if (((bi >> 3) & 31) == lane) v[bi & 7] = -FLT_MAX;   // owner invalidates
    }
    __syncthreads();

    // warp 0 merges 64 candidates -> global top-8
    if (w == 0) {
        float v0 = candV[lane], v1 = candV[lane + 32];
        int   i0 = candI[lane], i1 = candI[lane + 32];
        #pragma unroll
        for (int iter = 0; iter < 8; iter++) {
            float bv; int bi;
            if (v0 > v1 || (v0 == v1 && i0 < i1)) { bv = v0; bi = i0; }
            else                                  { bv = v1; bi = i1; }
            #pragma unroll
            for (int off = 16; off > 0; off >>= 1) {
                float ov = __shfl_down_sync(0xffffffffu, bv, off);
                int   oi = __shfl_down_sync(0xffffffffu, bi, off);
                if (ov > bv || (ov == bv && oi < bi)) { bv = ov; bi = oi; }
            }
            bi = __shfl_sync(0xffffffffu, bi, 0);
            if (lane == 0) finalI[iter] = bi;
            if (i0 == bi) v0 = -FLT_MAX;
            if (i1 == bi) v1 = -FLT_MAX;
        }
    }
    __syncthreads();
    if (t < 8) {
        int kk = finalI[t];
        Srow[kk] = g_c[b * SEQ + kk];          // replace with exp(correction)
    }
}

// ============================================================
// K3: column sums of exp'd scores (no exp, no max chain — pure bandwidth,
// S is L2-resident). 256 blocks, 4-way ILP, deterministic.
// ============================================================
__global__ void colsum_kernel()
{
    int b = blockIdx.z, seg = blockIdx.y;
    int col = blockIdx.x * 256 + threadIdx.x;
    const float* base = &g_S[(b * SEQ + seg * (SEQ / QSEG)) * SEQ + col];
    float a0 = 0.f, a1 = 0.f, a2 = 0.f, a3 = 0.f;
    #pragma unroll 4
    for (int r = 0; r < SEQ / QSEG; r += 4) {
        a0 += base[(r + 0) * SEQ];
        a1 += base[(r + 1) * SEQ];
        a2 += base[(r + 2) * SEQ];
        a3 += base[(r + 3) * SEQ];
    }
    g_part[seg][b * SEQ + col] = (a0 + a1) + (a2 + a3);
}

__global__ void finalize_kernel()
{
    int i = blockIdx.x * 256 + threadIdx.x;    // < BATCH*SEQ
    float z = 0.f;
    #pragma unroll
    for (int s = 0; s < QSEG; s++) z += g_part[s][i];
    g_w[i] = 1.0f / z;
}

// ============================================================
// K4: out[q,:] = sum_k P[q,k] * (V[k,:] * w[k])   (P already exp'd)
// 64q x 128d tile per block, BK=32, 256 threads, thread = 8q x 4d.
// q paired into f32x2 accumulators driven by fma.rn.f32x2 (2 FMA/instr).
// ============================================================
__global__ void out_gemm_kernel(const float* __restrict__ V, float* __restrict__ out)
{
    int b  = blockIdx.y;
    int q0 = blockIdx.x * 64;
    __shared__ float Ps[32][66];       // [kk][m], stride 66: 8B aligned, low conflict
    __shared__ float Vsh[32][128];     // [kk][d], pre-scaled by w[k]
    int t = threadIdx.x;
    int tx = t & 31, ty = t >> 5;
    int m0 = ty * 8, n0 = tx * 4;

    unsigned long long acc[4][4];
    #pragma unroll
    for (int pi = 0; pi < 4; pi++)
        #pragma unroll
        for (int jj = 0; jj < 4; jj++) acc[pi][jj] = 0ull;

    const float* Sbase = &g_S[(b * SEQ + q0) * SEQ];
    const float* Vbase = &V[b * SEQ * DMODEL];
    const float* wbase = &g_w[b * SEQ];

    for (int kt = 0; kt < SEQ; kt += 32) {
        {   // P tile 64x32 -> transposed smem (no exp needed)
            int q_l = t >> 3;
            int kg  = (t & 7) * 4;
            #pragma unroll
            for (int pass = 0; pass < 2; pass++) {
                int qq = q_l + pass * 32;
                float4 sv = *(const float4*)&Sbase[qq * SEQ + kt + kg];
                Ps[kg + 0][qq] = sv.x;
                Ps[kg + 1][qq] = sv.y;
                Ps[kg + 2][qq] = sv.z;
                Ps[kg + 3][qq] = sv.w;
            }
        }
        {   // V tile 32x128, scaled by w
            int row = t >> 5;
            int c0  = (t & 31) * 4;
            #pragma unroll
            for (int pass = 0; pass < 4; pass++) {
                int rr = row + pass * 8;
                float wk = wbase[kt + rr];
                float4 vv = *(const float4*)&Vbase[(kt + rr) * DMODEL + c0];
                vv.x *= wk; vv.y *= wk; vv.z *= wk; vv.w *= wk;
                *(float4*)&Vsh[rr][c0] = vv;
            }
        }
        __syncthreads();
        #pragma unroll
        for (int kk = 0; kk < 32; kk++) {
            unsigned long long ap[4];
            #pragma unroll
            for (int pi = 0; pi < 4; pi++)
                ap[pi] = *(const unsigned long long*)&Ps[kk][m0 + pi * 2];
            float4 bv = *(const float4*)&Vsh[kk][n0];
            unsigned long long bd[4];
            asm("mov.b64 %0, {%1, %1};" : "=l"(bd[0]) : "r"(__float_as_uint(bv.x)));
            asm("mov.b64 %0, {%1, %1};" : "=l"(bd[1]) : "r"(__float_as_uint(bv.y)));
            asm("mov.b64 %0, {%1, %1};" : "=l"(bd[2]) : "r"(__float_as_uint(bv.z)));
            asm("mov.b64 %0, {%1, %1};" : "=l"(bd[3]) : "r"(__float_as_uint(bv.w)));
            #pragma unroll
            for (int pi = 0; pi < 4; pi++)
                #pragma unroll
                for (int jj = 0; jj < 4; jj++)
                    asm("fma.rn.f32x2 %0, %1, %2, %0;"
                        : "+l"(acc[pi][jj]) : "l"(ap[pi]), "l"(bd[jj]));
        }
        __syncthreads();
    }
    #pragma unroll
    for (int pi = 0; pi < 4; pi++) {
        float4 lo4, hi4;
        float* lo = (float*)&lo4; float* hi = (float*)&hi4;
        #pragma unroll
        for (int jj = 0; jj < 4; jj++) {
            unsigned int l, h;
            asm("mov.b64 {%0, %1}, %2;" : "=r"(l), "=r"(h) : "l"(acc[pi][jj]));
            lo[jj] = __uint_as_float(l);
            hi[jj] = __uint_as_float(h);
        }
        int qa = q0 + m0 + pi * 2;
        *(float4*)&out[(b * SEQ + qa) * DMODEL + n0]     = lo4;
        *(float4*)&out[(b * SEQ + qa + 1) * DMODEL + n0] = hi4;
    }
}

// ============================================================
extern "C" void kernel_launch(void* const* d_in, const int* in_sizes, int n_in,
                              void* d_out, int out_size)
{
    const float* queries = (const float*)d_in[0];
    const float* keys    = (const float*)d_in[1];
    const float* values  = (const float*)d_in[2];
    const int*   vlens   = (const int*)  d_in[3];
    const float* Wql     = (const float*)d_in[4];
    const float* bql     = (const float*)d_in[5];
    const float* Wkl     = (const float*)d_in[6];
    const float* bkl     = (const float*)d_in[7];
    const float* Wqh     = (const float*)d_in[8];
    const float* bqh     = (const float*)d_in[9];
    const float* Wkh     = (const float*)d_in[10];
    const float* bkh     = (const float*)d_in[11];
    float* out = (float*)d_out;

    proj_kernel<<<BATCH * SEQ, 64>>>(queries, keys, Wql, bql, Wkl, bkl,
                                     Wqh, bqh, Wkh, bkh);
    scores_kernel<<<dim3(SEQ / 128, SEQ / 64, BATCH), 256>>>(vlens);
    topk_kernel<<<dim3(SEQ, BATCH), 256>>>();
    colsum_kernel<<<dim3(SEQ / 256, QSEG, BATCH), 256>>>();
    finalize_kernel<<<BATCH * SEQ / 256, 256>>>();
    out_gemm_kernel<<<dim3(SEQ / 64, BATCH), 256>>>(values, out);
}

// round 6
// speedup vs baseline: 1.2552x; 1.1189x over previous
#include <cuda_runtime.h>
#include <cstdint>
#include <cfloat>

#define BATCH 4
#define SEQ   2048
#define DMODEL 128
#define DLOW  16
#define NEGV  (-1e9f)
#define SCALE 0.25f
#define NQB   32            // q-blocks per batch in scores kernel (SEQ/64)

// ---- scratch (static __device__, no allocations) ----
__device__ float g_S[BATCH * SEQ * SEQ];          // 64 MB: exp(corrected scores)
__device__ float g_qlow[BATCH * SEQ * DLOW];
__device__ float g_klowT[BATCH * DLOW * SEQ];
__device__ float g_c[BATCH * SEQ];                // exp(correction score)
__device__ float g_w[BATCH * SEQ];                // 1 / column Z
__device__ float g_part[NQB][BATCH * SEQ];        // column-sum partials (pre-scatter)
__device__ float g_Zadj[BATCH * SEQ];             // scatter corrections (atomic)

// ============================================================
__global__ void zero_kernel()
{
    g_Zadj[blockIdx.x * 256 + threadIdx.x] = 0.f;
}

// ============================================================
// K1: projections. One block (64 threads) per (b, position).
// ============================================================
__global__ void proj_kernel(const float* __restrict__ q, const float* __restrict__ k,
                            const float* __restrict__ Wql, const float* __restrict__ bql,
                            const float* __restrict__ Wkl, const float* __restrict__ bkl,
                            const float* __restrict__ Wqh, const float* __restrict__ bqh,
                            const float* __restrict__ Wkh, const float* __restrict__ bkh)
{
    int p = blockIdx.x;
    int b = p >> 11, i = p & (SEQ - 1);
    __shared__ float qs[DMODEL], ks[DMODEL];
    __shared__ float qh[DLOW], kh[DLOW];
    int t = threadIdx.x;
    {
        float2 qv = *(const float2*)&q[p * DMODEL + t * 2];
        qs[t * 2] = qv.x; qs[t * 2 + 1] = qv.y;
        float2 kv = *(const float2*)&k[p * DMODEL + t * 2];
        ks[t * 2] = kv.x; ks[t * 2 + 1] = kv.y;
    }
    __syncthreads();
    int j = t & 15;
    int which = t >> 4;
    const float* W; const float* bias; const float* src;
    if (which == 0)      { W = Wql; bias = bql; src = qs; }
    else if (which == 1) { W = Wkl; bias = bkl; src = ks; }
    else if (which == 2) { W = Wqh; bias = bqh; src = qs; }
    else                 { W = Wkh; bias = bkh; src = ks; }
    float acc = bias[j];
    #pragma unroll 16
    for (int d0 = 0; d0 < DMODEL; d0++)
        acc = fmaf(src[d0], W[d0 * DLOW + j], acc);
    if (which == 0)      g_qlow[p * DLOW + j] = acc;
    else if (which == 1) g_klowT[(b * DLOW + j) * SEQ + i] = acc;
    else if (which == 2) qh[j] = acc;
    else                 kh[j] = acc;
    __syncthreads();
    if (t == 0) {
        float c = 0.f;
        #pragma unroll
        for (int jj = 0; jj < DLOW; jj++) c = fmaf(qh[jj], kh[jj], c);
        g_c[p] = __expf(c * SCALE);
    }
}

// ============================================================
// K2a: exp(masked low-rank scores) + in-register column partial sums.
// block: 64q x 128k tile, 256 threads, thread = 8x4.
// ============================================================
__global__ void scores_kernel(const int* __restrict__ valid_lens)
{
    int b  = blockIdx.z;
    int q0 = blockIdx.y * 64;
    int k0 = blockIdx.x * 128;
    __shared__ float qT[DLOW][64];
    __shared__ float kS[DLOW][128];
    __shared__ float redsm[8][128];
    int t = threadIdx.x;
    {
        int row = t >> 2, j0 = (t & 3) * 4;
        const float4 v = *(const float4*)&g_qlow[(b * SEQ + q0 + row) * DLOW + j0];
        qT[j0 + 0][row] = v.x; qT[j0 + 1][row] = v.y;
        qT[j0 + 2][row] = v.z; qT[j0 + 3][row] = v.w;
    }
    {
        int row = t >> 5, c0 = (t & 31) * 4;
        #pragma unroll
        for (int r = 0; r < DLOW; r += 8)
            *(float4*)&kS[row + r][c0] =
                *(const float4*)&g_klowT[(b * DLOW + row + r) * SEQ + k0 + c0];
    }
    __syncthreads();
    int tx = t & 31, ty = t >> 5;
    int m0 = ty * 8, n0 = tx * 4;
    float acc[8][4];
    #pragma unroll
    for (int i = 0; i < 8; i++)
        #pragma unroll
        for (int jj = 0; jj < 4; jj++) acc[i][jj] = 0.f;
    #pragma unroll
    for (int j = 0; j < DLOW; j++) {
        float a[8];
        *(float4*)&a[0] = *(const float4*)&qT[j][m0];
        *(float4*)&a[4] = *(const float4*)&qT[j][m0 + 4];
        float4 bv = *(const float4*)&kS[j][n0];
        #pragma unroll
        for (int i = 0; i < 8; i++) {
            acc[i][0] = fmaf(a[i], bv.x, acc[i][0]);
            acc[i][1] = fmaf(a[i], bv.y, acc[i][1]);
            acc[i][2] = fmaf(a[i], bv.z, acc[i][2]);
            acc[i][3] = fmaf(a[i], bv.w, acc[i][3]);
        }
    }
    int vl[4];
    #pragma unroll
    for (int jj = 0; jj < 4; jj++) {
        int v = valid_lens[b * SEQ + k0 + n0 + jj];
        vl[jj] = min(max(v, 0), SEQ - 1);
    }
    float cs[4] = {0.f, 0.f, 0.f, 0.f};
    #pragma unroll
    for (int i = 0; i < 8; i++) {
        int qrow = q0 + m0 + i;
        float4 o; float* po = (float*)&o;
        #pragma unroll
        for (int jj = 0; jj < 4; jj++) {
            float v = acc[i][jj] * SCALE;
            if (vl[jj] == qrow) v += NEGV;
            float e = __expf(v);
            po[jj] = e;
            cs[jj] += e;
        }
        *(float4*)&g_S[(b * SEQ + qrow) * SEQ + k0 + n0] = o;
    }
    #pragma unroll
    for (int jj = 0; jj < 4; jj++) redsm[ty][n0 + jj] = cs[jj];
    __syncthreads();
    if (t < 128) {
        float s = 0.f;
        #pragma unroll
        for (int r = 0; r < 8; r++) s += redsm[r][t];
        g_part[blockIdx.y][b * SEQ + k0 + t] = s;
    }
}

// ============================================================
// K2b: per-row top-8 on exp'd scores; merge warp scatters exp(c)
// and emits Z corrections (atomic delta per touched column).
// ============================================================
__global__ void topk_kernel()
{
    int b = blockIdx.y, qrow = blockIdx.x;
    float* Srow = &g_S[(b * SEQ + qrow) * SEQ];
    __shared__ float candV[64];
    __shared__ int   candI[64];
    int t = threadIdx.x, lane = t & 31, w = t >> 5;
    int base = w * 256 + lane * 8;
    float v[8];
    *(float4*)&v[0] = *(const float4*)&Srow[base];
    *(float4*)&v[4] = *(const float4*)&Srow[base + 4];

    #pragma unroll
    for (int iter = 0; iter < 8; iter++) {
        float bv = -FLT_MAX; int bi = 0x7fffffff;
        #pragma unroll
        for (int jj = 0; jj < 8; jj++)
            if (v[jj] > bv) { bv = v[jj]; bi = base + jj; }
        #pragma unroll
        for (int off = 16; off > 0; off >>= 1) {
            float ov = __shfl_down_sync(0xffffffffu, bv, off);
            int   oi = __shfl_down_sync(0xffffffffu, bi, off);
            if (ov > bv || (ov == bv && oi < bi)) { bv = ov; bi = oi; }
        }
        bv = __shfl_sync(0xffffffffu, bv, 0);
        bi = __shfl_sync(0xffffffffu, bi, 0);
        if (lane == 0) { candV[w * 8 + iter] = bv; candI[w * 8 + iter] = bi; }
        if (((bi >> 3) & 31) == lane) v[bi & 7] = -FLT_MAX;
    }
    __syncthreads();

    if (w == 0) {
        float v0 = candV[lane], v1 = candV[lane + 32];
        int   i0 = candI[lane], i1 = candI[lane + 32];
        #pragma unroll
        for (int iter = 0; iter < 8; iter++) {
            float bv; int bi;
            if (v0 > v1 || (v0 == v1 && i0 < i1)) { bv = v0; bi = i0; }
            else                                  { bv = v1; bi = i1; }
            #pragma unroll
            for (int off = 16; off > 0; off >>= 1) {
                float ov = __shfl_down_sync(0xffffffffu, bv, off);
                int   oi = __shfl_down_sync(0xffffffffu, bi, off);
                if (ov > bv || (ov == bv && oi < bi)) { bv = ov; bi = oi; }
            }
            bi = __shfl_sync(0xffffffffu, bi, 0);
            if (lane == 0) {
                float ec = g_c[b * SEQ + bi];
                Srow[bi] = ec;                          // replace with exp(correction)
                atomicAdd(&g_Zadj[b * SEQ + bi], ec - bv);
            }
            if (i0 == bi) v0 = -FLT_MAX;
            if (i1 == bi) v1 = -FLT_MAX;
        }
    }
}

// ============================================================
// K3: w = 1 / (sum of partials + scatter corrections)
// ============================================================
__global__ void finalize_kernel()
{
    int i = blockIdx.x * 256 + threadIdx.x;
    float z = g_Zadj[i];
    #pragma unroll
    for (int s = 0; s < NQB; s++) z += g_part[s][i];
    g_w[i] = 1.0f / z;
}

// ============================================================
// K4: out[q,:] = sum_k P[q,k] * (V[k,:] * w[k]) — double-buffered FFMA2 GEMM
// 64q x 128d tile, BK=32, 256 threads, thread = 8q x 4d, f32x2 acc pairs.
// ============================================================
#define PS_STRIDE 66
#define PS_TILE   (32 * PS_STRIDE)
#define VS_TILE   (32 * 128)
#define OG_SMEM   ((2 * (PS_TILE + VS_TILE)) * 4)

__global__ void __launch_bounds__(256) out_gemm_kernel(const float* __restrict__ V,
                                                       float* __restrict__ out)
{
    extern __shared__ float sm[];
    float* Ps = sm;                     // [2][32][PS_STRIDE], transposed (kk-major)
    float* Vs = sm + 2 * PS_TILE;       // [2][32][128], pre-scaled by w

    int b  = blockIdx.y;
    int q0 = blockIdx.x * 64;
    int t = threadIdx.x;
    int tx = t & 31, ty = t >> 5;
    int m0 = ty * 8, n0 = tx * 4;

    const float* Sbase = &g_S[(b * SEQ + q0) * SEQ];
    const float* Vbase = &V[b * SEQ * DMODEL];
    const float* wbase = &g_w[b * SEQ];

    // load-thread coords
    int p_q  = t >> 3;             // 0..31
    int p_kg = (t & 7) * 4;        // 0..28
    int v_r  = t >> 5;             // 0..7
    int v_c  = (t & 31) * 4;       // 0..124

    unsigned long long acc[4][4];
    #pragma unroll
    for (int pi = 0; pi < 4; pi++)
        #pragma unroll
        for (int jj = 0; jj < 4; jj++) acc[pi][jj] = 0ull;

    float4 pP[2], pV[4];
    float  pW[4];

    // ---- prologue: load tile 0 ----
    #pragma unroll
    for (int pass = 0; pass < 2; pass++)
        pP[pass] = *(const float4*)&Sbase[(p_q + pass * 32) * SEQ + p_kg];
    #pragma unroll
    for (int pass = 0; pass < 4; pass++) {
        int rr = v_r + pass * 8;
        pW[pass] = wbase[rr];
        pV[pass] = *(const float4*)&Vbase[rr * DMODEL + v_c];
    }
    {
        float* P0 = Ps;
        float* V0 = Vs;
        #pragma unroll
        for (int pass = 0; pass < 2; pass++) {
            int qq = p_q + pass * 32;
            P0[(p_kg + 0) * PS_STRIDE + qq] = pP[pass].x;
            P0[(p_kg + 1) * PS_STRIDE + qq] = pP[pass].y;
            P0[(p_kg + 2) * PS_STRIDE + qq] = pP[pass].z;
            P0[(p_kg + 3) * PS_STRIDE + qq] = pP[pass].w;
        }
        #pragma unroll
        for (int pass = 0; pass < 4; pass++) {
            int rr = v_r + pass * 8;
            float4 vv = pV[pass];
            float wk = pW[pass];
            vv.x *= wk; vv.y *= wk; vv.z *= wk; vv.w *= wk;
            *(float4*)&V0[rr * 128 + v_c] = vv;
        }
    }
    __syncthreads();

    const int NKT = SEQ / 32;
    for (int kt_i = 0; kt_i < NKT; kt_i++) {
        int cur = kt_i & 1;
        // prefetch next tile's globals
        if (kt_i + 1 < NKT) {
            int kt = (kt_i + 1) * 32;
            #pragma unroll
            for (int pass = 0; pass < 2; pass++)
                pP[pass] = *(const float4*)&Sbase[(p_q + pass * 32) * SEQ + kt + p_kg];
            #pragma unroll
            for (int pass = 0; pass < 4; pass++) {
                int rr = kt + v_r + pass * 8;
                pW[pass] = wbase[rr];
                pV[pass] = *(const float4*)&Vbase[rr * DMODEL + v_c];
            }
        }
        // compute from current buffer
        float* Pc = Ps + cur * PS_TILE;
        float* Vc = Vs + cur * VS_TILE;
        #pragma unroll
        for (int kk = 0; kk < 32; kk++) {
            unsigned long long ap[4];
            #pragma unroll
            for (int pi = 0; pi < 4; pi++)
                ap[pi] = *(const unsigned long long*)&Pc[kk * PS_STRIDE + m0 + pi * 2];
            float4 bv = *(const float4*)&Vc[kk * 128 + n0];
            unsigned long long bd[4];
            asm("mov.b64 %0, {%1, %1};" : "=l"(bd[0]) : "r"(__float_as_uint(bv.x)));
            asm("mov.b64 %0, {%1, %1};" : "=l"(bd[1]) : "r"(__float_as_uint(bv.y)));
            asm("mov.b64 %0, {%1, %1};" : "=l"(bd[2]) : "r"(__float_as_uint(bv.z)));
            asm("mov.b64 %0, {%1, %1};" : "=l"(bd[3]) : "r"(__float_as_uint(bv.w)));
            #pragma unroll
            for (int pi = 0; pi < 4; pi++)
                #pragma unroll
                for (int jj = 0; jj < 4; jj++)
                    asm("fma.rn.f32x2 %0, %1, %2, %0;"
                        : "+l"(acc[pi][jj]) : "l"(ap[pi]), "l"(bd[jj]));
        }
        // store next tile into the other buffer
        if (kt_i + 1 < NKT) {
            float* Pn = Ps + (cur ^ 1) * PS_TILE;
            float* Vn = Vs + (cur ^ 1) * VS_TILE;
            #pragma unroll
            for (int pass = 0; pass < 2; pass++) {
                int qq = p_q + pass * 32;
                Pn[(p_kg + 0) * PS_STRIDE + qq] = pP[pass].x;
                Pn[(p_kg + 1) * PS_STRIDE + qq] = pP[pass].y;
                Pn[(p_kg + 2) * PS_STRIDE + qq] = pP[pass].z;
                Pn[(p_kg + 3) * PS_STRIDE + qq] = pP[pass].w;
            }
            #pragma unroll
            for (int pass = 0; pass < 4; pass++) {
                int rr = v_r + pass * 8;
                float4 vv = pV[pass];
                float wk = pW[pass];
                vv.x *= wk; vv.y *= wk; vv.z *= wk; vv.w *= wk;
                *(float4*)&Vn[rr * 128 + v_c] = vv;
            }
        }
        __syncthreads();
    }

    #pragma unroll
    for (int pi = 0; pi < 4; pi++) {
        float4 lo4, hi4;
        float* lo = (float*)&lo4; float* hi = (float*)&hi4;
        #pragma unroll
        for (int jj = 0; jj < 4; jj++) {
            unsigned int l, h;
            asm("mov.b64 {%0, %1}, %2;" : "=r"(l), "=r"(h) : "l"(acc[pi][jj]));
            lo[jj] = __uint_as_float(l);
            hi[jj] = __uint_as_float(h);
        }
        int qa = q0 + m0 + pi * 2;
        *(float4*)&out[(b * SEQ + qa) * DMODEL + n0]     = lo4;
        *(float4*)&out[(b * SEQ + qa + 1) * DMODEL + n0] = hi4;
    }
}

// ============================================================
extern "C" void kernel_launch(void* const* d_in, const int* in_sizes, int n_in,
                              void* d_out, int out_size)
{
    const float* queries = (const float*)d_in[0];
    const float* keys    = (const float*)d_in[1];
    const float* values  = (const float*)d_in[2];
    const int*   vlens   = (const int*)  d_in[3];
    const float* Wql     = (const float*)d_in[4];
    const float* bql     = (const float*)d_in[5];
    const float* Wkl     = (const float*)d_in[6];
    const float* bkl     = (const float*)d_in[7];
    const float* Wqh     = (const float*)d_in[8];
    const float* bqh     = (const float*)d_in[9];
    const float* Wkh     = (const float*)d_in[10];
    const float* bkh     = (const float*)d_in[11];
    float* out = (float*)d_out;

    static bool attr_set = false;
    if (!attr_set) {
        cudaFuncSetAttribute(out_gemm_kernel,
                             cudaFuncAttributeMaxDynamicSharedMemorySize, OG_SMEM);
        attr_set = true;
    }

    zero_kernel<<<BATCH * SEQ / 256, 256>>>();
    proj_kernel<<<BATCH * SEQ, 64>>>(queries, keys, Wql, bql, Wkl, bkl,
                                     Wqh, bqh, Wkh, bkh);
    scores_kernel<<<dim3(SEQ / 128, SEQ / 64, BATCH), 256>>>(vlens);
    topk_kernel<<<dim3(SEQ, BATCH), 256>>>();
    finalize_kernel<<<BATCH * SEQ / 256, 256>>>();
    out_gemm_kernel<<<dim3(SEQ / 64, BATCH), 256, OG_SMEM>>>(values, out);
}

// round 10
// speedup vs baseline: 1.7975x; 1.4320x over previous
#include <cuda_runtime.h>
#include <cuda_bf16.h>
#include <cstdint>
#include <cfloat>

#define BATCH 4
#define SEQ   2048
#define DMODEL 128
#define DLOW  16
#define NEGV  (-1e9f)
#define SCALE 0.25f
#define NQB   32

// ---- scratch (static __device__, no allocations) ----
__device__ float g_S[BATCH * SEQ * SEQ];          // 64 MB: exp(corrected scores)
__device__ float g_qlow[BATCH * SEQ * DLOW];
__device__ float g_klowT[BATCH * DLOW * SEQ];
__device__ float g_c[BATCH * SEQ];                // exp(correction score)
__device__ float g_w[BATCH * SEQ];                // 1 / column Z
__device__ float g_part[NQB][BATCH * SEQ];
__device__ float g_Zadj[BATCH * SEQ];
__device__ __nv_bfloat16 g_VhT[BATCH * DMODEL * SEQ];   // (V*w)^T hi, [b][d][k]
__device__ __nv_bfloat16 g_VlT[BATCH * DMODEL * SEQ];   // (V*w)^T lo

// ============================================================
__global__ void zero_kernel()
{
    g_Zadj[blockIdx.x * 256 + threadIdx.x] = 0.f;
}

// ============================================================
// K1: projections. One block (64 threads) per (b, position).
// ============================================================
__global__ void proj_kernel(const float* __restrict__ q, const float* __restrict__ k,
                            const float* __restrict__ Wql, const float* __restrict__ bql,
                            const float* __restrict__ Wkl, const float* __restrict__ bkl,
                            const float* __restrict__ Wqh, const float* __restrict__ bqh,
                            const float* __restrict__ Wkh, const float* __restrict__ bkh)
{
    int p = blockIdx.x;
    int b = p >> 11, i = p & (SEQ - 1);
    __shared__ float qs[DMODEL], ks[DMODEL];
    __shared__ float qh[DLOW], kh[DLOW];
    int t = threadIdx.x;
    {
        float2 qv = *(const float2*)&q[p * DMODEL + t * 2];
        qs[t * 2] = qv.x; qs[t * 2 + 1] = qv.y;
        float2 kv = *(const float2*)&k[p * DMODEL + t * 2];
        ks[t * 2] = kv.x; ks[t * 2 + 1] = kv.y;
    }
    __syncthreads();
    int j = t & 15;
    int which = t >> 4;
    const float* W; const float* bias; const float* src;
    if (which == 0)      { W = Wql; bias = bql; src = qs; }
    else if (which == 1) { W = Wkl; bias = bkl; src = ks; }
    else if (which == 2) { W = Wqh; bias = bqh; src = qs; }
    else                 { W = Wkh; bias = bkh; src = ks; }
    float acc = bias[j];
    #pragma unroll 16
    for (int d0 = 0; d0 < DMODEL; d0++)
        acc = fmaf(src[d0], W[d0 * DLOW + j], acc);
    if (which == 0)      g_qlow[p * DLOW + j] = acc;
    else if (which == 1) g_klowT[(b * DLOW + j) * SEQ + i] = acc;
    else if (which == 2) qh[j] = acc;
    else                 kh[j] = acc;
    __syncthreads();
    if (t == 0) {
        float c = 0.f;
        #pragma unroll
        for (int jj = 0; jj < DLOW; jj++) c = fmaf(qh[jj], kh[jj], c);
        g_c[p] = __expf(c * SCALE);
    }
}

// ============================================================
// K2a: exp(masked low-rank scores) + column partial sums.
// ============================================================
__global__ void scores_kernel(const int* __restrict__ valid_lens)
{
    int b  = blockIdx.z;
    int q0 = blockIdx.y * 64;
    int k0 = blockIdx.x * 128;
    __shared__ float qT[DLOW][64];
    __shared__ float kS[DLOW][128];
    __shared__ float redsm[8][128];
    int t = threadIdx.x;
    {
        int row = t >> 2, j0 = (t & 3) * 4;
        const float4 v = *(const float4*)&g_qlow[(b * SEQ + q0 + row) * DLOW + j0];
        qT[j0 + 0][row] = v.x; qT[j0 + 1][row] = v.y;
        qT[j0 + 2][row] = v.z; qT[j0 + 3][row] = v.w;
    }
    {
        int row = t >> 5, c0 = (t & 31) * 4;
        #pragma unroll
        for (int r = 0; r < DLOW; r += 8)
            *(float4*)&kS[row + r][c0] =
                *(const float4*)&g_klowT[(b * DLOW + row + r) * SEQ + k0 + c0];
    }
    __syncthreads();
    int tx = t & 31, ty = t >> 5;
    int m0 = ty * 8, n0 = tx * 4;
    float acc[8][4];
    #pragma unroll
    for (int i = 0; i < 8; i++)
        #pragma unroll
        for (int jj = 0; jj < 4; jj++) acc[i][jj] = 0.f;
    #pragma unroll
    for (int j = 0; j < DLOW; j++) {
        float a[8];
        *(float4*)&a[0] = *(const float4*)&qT[j][m0];
        *(float4*)&a[4] = *(const float4*)&qT[j][m0 + 4];
        float4 bv = *(const float4*)&kS[j][n0];
        #pragma unroll
        for (int i = 0; i < 8; i++) {
            acc[i][0] = fmaf(a[i], bv.x, acc[i][0]);
            acc[i][1] = fmaf(a[i], bv.y, acc[i][1]);
            acc[i][2] = fmaf(a[i], bv.z, acc[i][2]);
            acc[i][3] = fmaf(a[i], bv.w, acc[i][3]);
        }
    }
    int vl[4];
    #pragma unroll
    for (int jj = 0; jj < 4; jj++) {
        int v = valid_lens[b * SEQ + k0 + n0 + jj];
        vl[jj] = min(max(v, 0), SEQ - 1);
    }
    float cs[4] = {0.f, 0.f, 0.f, 0.f};
    #pragma unroll
    for (int i = 0; i < 8; i++) {
        int qrow = q0 + m0 + i;
        float4 o; float* po = (float*)&o;
        #pragma unroll
        for (int jj = 0; jj < 4; jj++) {
            float v = acc[i][jj] * SCALE;
            if (vl[jj] == qrow) v += NEGV;
            float e = __expf(v);
            po[jj] = e;
            cs[jj] += e;
        }
        *(float4*)&g_S[(b * SEQ + qrow) * SEQ + k0 + n0] = o;
    }
    #pragma unroll
    for (int jj = 0; jj < 4; jj++) redsm[ty][n0 + jj] = cs[jj];
    __syncthreads();
    if (t < 128) {
        float s = 0.f;
        #pragma unroll
        for (int r = 0; r < 8; r++) s += redsm[r][t];
        g_part[blockIdx.y][b * SEQ + k0 + t] = s;
    }
}

// ============================================================
// K2b: exact threshold-based top-8.
// T = 8th-largest of 64 chunk maxima => >=8 elems >= T and top-8 all >= T.
// Collect candidates >= T (buffer = 2048, unconditionally exact), then
// exact top-8 with (value desc, idx asc) tie-break; scatter + Zadj.
// ============================================================
__global__ void topk_kernel()
{
    int b = blockIdx.y, qrow = blockIdx.x;
    float* Srow = &g_S[(b * SEQ + qrow) * SEQ];
    __shared__ float chmax[64];
    __shared__ float Tsh;
    __shared__ int   ncand;
    __shared__ float candV[2048];
    __shared__ int   candI[2048];
    int t = threadIdx.x, lane = t & 31, w = t >> 5;
    if (t == 0) ncand = 0;
    int base = t * 8;
    float v[8];
    *(float4*)&v[0] = *(const float4*)&Srow[base];
    *(float4*)&v[4] = *(const float4*)&Srow[base + 4];
    float lm = fmaxf(fmaxf(fmaxf(v[0], v[1]), fmaxf(v[2], v[3])),
                     fmaxf(fmaxf(v[4], v[5]), fmaxf(v[6], v[7])));
    lm = fmaxf(lm, __shfl_xor_sync(0xffffffffu, lm, 1));
    lm = fmaxf(lm, __shfl_xor_sync(0xffffffffu, lm, 2));
    if ((t & 3) == 0) chmax[t >> 2] = lm;
    __syncthreads();
    if (w == 0) {
        float a = chmax[lane], c = chmax[lane + 32];
        float T = 0.f;
        #pragma unroll
        for (int it = 0; it < 8; it++) {
            float m = fmaxf(a, c);
            #pragma unroll
            for (int off = 16; off > 0; off >>= 1)
                m = fmaxf(m, __shfl_xor_sync(0xffffffffu, m, off));
            T = m;
            unsigned ba = __ballot_sync(0xffffffffu, a == m);
            if (ba) {
                if (lane == __ffs(ba) - 1) a = -FLT_MAX;
            } else {
                unsigned bc = __ballot_sync(0xffffffffu, c == m);
                if (lane == __ffs(bc) - 1) c = -FLT_MAX;
            }
        }
        if (lane == 0) Tsh = T;
    }
    __syncthreads();
    float T = Tsh;
    #pragma unroll
    for (int jj = 0; jj < 8; jj++) {
        if (v[jj] >= T) {
            int p = atomicAdd(&ncand, 1);
            candV[p] = v[jj];
            candI[p] = base + jj;
        }
    }
    __syncthreads();
    int nc = ncand;
    if (w == 0) {
        #pragma unroll 1
        for (int it = 0; it < 8; it++) {
            float bv = -FLT_MAX; int bi = 0x7fffffff;
            for (int p = lane; p < nc; p += 32) {
                float cv = candV[p]; int ci = candI[p];
                if (cv > bv || (cv == bv && ci < bi)) { bv = cv; bi = ci; }
            }
            #pragma unroll
            for (int off = 16; off > 0; off >>= 1) {
                float ov = __shfl_xor_sync(0xffffffffu, bv, off);
                int   oi = __shfl_xor_sync(0xffffffffu, bi, off);
                if (ov > bv || (ov == bv && oi < bi)) { bv = ov; bi = oi; }
            }
            for (int p = lane; p < nc; p += 32)
                if (candI[p] == bi) candV[p] = -FLT_MAX;
            if (lane == 0) {
                float ec = g_c[b * SEQ + bi];
                Srow[bi] = ec;
                atomicAdd(&g_Zadj[b * SEQ + bi], ec - bv);
            }
            __syncwarp();
        }
    }
}

// ============================================================
// K3: w = 1 / (sum of partials + scatter corrections)
// ============================================================
__global__ void finalize_kernel()
{
    int i = blockIdx.x * 256 + threadIdx.x;
    float z = g_Zadj[i];
    #pragma unroll
    for (int s = 0; s < NQB; s++) z += g_part[s][i];
    g_w[i] = 1.0f / z;
}

// ============================================================
// K3b: (V*w)^T split into bf16 hi/lo, [b][d][k] layout.
// block: 32k x 128d tile, 256 threads.
// ============================================================
__global__ void vconv_kernel(const float* __restrict__ V)
{
    int b = blockIdx.y, k0 = blockIdx.x * 32;
    __shared__ float vs[32][129];
    int t = threadIdx.x;
    {
        int r = t >> 3, c0 = (t & 7) * 16;
        float wk = g_w[b * SEQ + k0 + r];
        #pragma unroll
        for (int qd = 0; qd < 4; qd++) {
            float4 vv = *(const float4*)&V[(b * SEQ + k0 + r) * DMODEL + c0 + qd * 4];
            vs[r][c0 + qd * 4 + 0] = vv.x * wk;
            vs[r][c0 + qd * 4 + 1] = vv.y * wk;
            vs[r][c0 + qd * 4 + 2] = vv.z * wk;
            vs[r][c0 + qd * 4 + 3] = vv.w * wk;
        }
    }
    __syncthreads();
    int d = t >> 1, kh = (t & 1) * 16;
    uint4 hq[2], lq[2];
    __nv_bfloat162* hp = (__nv_bfloat162*)hq;
    __nv_bfloat162* lp = (__nv_bfloat162*)lq;
    #pragma unroll
    for (int i = 0; i < 8; i++) {
        float x0 = vs[kh + 2 * i][d], x1 = vs[kh + 2 * i + 1][d];
        __nv_bfloat16 h0 = __float2bfloat16(x0), h1 = __float2bfloat16(x1);
        hp[i] = __halves2bfloat162(h0, h1);
        lp[i] = __halves2bfloat162(__float2bfloat16(x0 - __bfloat162float(h0)),
                                   __float2bfloat16(x1 - __bfloat162float(h1)));
    }
    __nv_bfloat16* dsth = &g_VhT[(b * DMODEL + d) * SEQ + k0 + kh];
    *(uint4*)dsth = hq[0];
    *((uint4*)dsth + 1) = hq[1];
    __nv_bfloat16* dstl = &g_VlT[(b * DMODEL + d) * SEQ + k0 + kh];
    *(uint4*)dstl = lq[0];
    *((uint4*)dstl + 1) = lq[1];
}

// ============================================================
// K4: tensor-core output GEMM with split-bf16 compensation.
// out = P @ (V*w), P fp32 -> (Ph + Pl), Vw -> (Vh + Vl);
// D += PhVh + PhVl + PlVh  (PlVl ~ 2^-18, dropped).
// Block 64q x 128d, 8 warps as 2(m) x 4(n), warp tile 32x32,
// mma.sync.m16n8k16 bf16, double-buffered smem.
// ============================================================
#define PST   40                     // smem k-stride (bf16 elems), conflict-free
#define P_SZ  (64 * PST)             // 2560
#define V_SZ  (128 * PST)            // 5120
#define BUFE  (2 * P_SZ + 2 * V_SZ)  // 15360 elems per buffer
#define MMA_SMEM (2 * BUFE * 2)      // 61440 bytes

#define MMA_OP(c, a, bb) \
    asm volatile("mma.sync.aligned.m16n8k16.row.col.f32.bf16.bf16.f32 " \
        "{%0,%1,%2,%3}, {%4,%5,%6,%7}, {%8,%9}, {%0,%1,%2,%3};" \
        : "+f"((c)[0]), "+f"((c)[1]), "+f"((c)[2]), "+f"((c)[3]) \
        : "r"((a)[0]), "r"((a)[1]), "r"((a)[2]), "r"((a)[3]), \
          "r"((bb)[0]), "r"((bb)[1]))

__global__ void __launch_bounds__(256) out_gemm_mma(float* __restrict__ out)
{
    extern __shared__ __nv_bfloat16 smb[];
    int b = blockIdx.y, q0 = blockIdx.x * 64;
    int t = threadIdx.x, lane = t & 31, w = t >> 5;
    int g = lane >> 2, tq = lane & 3;
    int wm = w >> 2, wn = w & 3;                 // 2 x 4 warp grid

    const float* Sbase = &g_S[(b * SEQ + q0) * SEQ];
    const __nv_bfloat16* VhB = &g_VhT[b * DMODEL * SEQ];
    const __nv_bfloat16* VlB = &g_VlT[b * DMODEL * SEQ];

    int s_q = t >> 2, s_k = (t & 3) * 8;         // S tile: 64 x 32 fp32
    int v_d = t >> 1, v_k = (t & 1) * 16;        // V tiles: 128 x 32 bf16

    float acc[2][4][4];
    #pragma unroll
    for (int mt = 0; mt < 2; mt++)
        #pragma unroll
        for (int nt = 0; nt < 4; nt++)
            #pragma unroll
            for (int x = 0; x < 4; x++) acc[mt][nt][x] = 0.f;

    float4 sP[2]; uint4 sVh[2], sVl[2];

    auto LOADG = [&](int kt) {
        sP[0] = *(const float4*)&Sbase[s_q * SEQ + kt + s_k];
        sP[1] = *(const float4*)&Sbase[s_q * SEQ + kt + s_k + 4];
        const uint4* ph = (const uint4*)&VhB[v_d * SEQ + kt + v_k];
        sVh[0] = ph[0]; sVh[1] = ph[1];
        const uint4* pl = (const uint4*)&VlB[v_d * SEQ + kt + v_k];
        sVl[0] = pl[0]; sVl[1] = pl[1];
    };
    auto STORES = [&](int buf) {
        __nv_bfloat16* Ph = smb + buf * BUFE;
        __nv_bfloat16* Pl = Ph + P_SZ;
        __nv_bfloat16* Vh = Ph + 2 * P_SZ;
        __nv_bfloat16* Vl = Vh + V_SZ;
        float f[8];
        *(float4*)&f[0] = sP[0]; *(float4*)&f[4] = sP[1];
        uint4 hq, lq;
        __nv_bfloat162* hp = (__nv_bfloat162*)&hq;
        __nv_bfloat162* lp = (__nv_bfloat162*)&lq;
        #pragma unroll
        for (int i = 0; i < 4; i++) {
            __nv_bfloat16 h0 = __float2bfloat16(f[2 * i]);
            __nv_bfloat16 h1 = __float2bfloat16(f[2 * i + 1]);
            hp[i] = __halves2bfloat162(h0, h1);
            lp[i] = __halves2bfloat162(
                __float2bfloat16(f[2 * i] - __bfloat162float(h0)),
                __float2bfloat16(f[2 * i + 1] - __bfloat162float(h1)));
        }
        *(uint4*)&Ph[s_q * PST + s_k] = hq;
        *(uint4*)&Pl[s_q * PST + s_k] = lq;
        *(uint4*)&Vh[v_d * PST + v_k]     = sVh[0];
        *(uint4*)&Vh[v_d * PST + v_k + 8] = sVh[1];
        *(uint4*)&Vl[v_d * PST + v_k]     = sVl[0];
        *(uint4*)&Vl[v_d * PST + v_k + 8] = sVl[1];
    };
    auto COMPUTE = [&](int buf) {
        const __nv_bfloat16* Ph = smb + buf * BUFE;
        const __nv_bfloat16* Pl = Ph + P_SZ;
        const __nv_bfloat16* Vh = Ph + 2 * P_SZ;
        const __nv_bfloat16* Vl = Vh + V_SZ;
        #pragma unroll
        for (int ks = 0; ks < 32; ks += 16) {
            uint32_t ah[2][4], al[2][4];
            #pragma unroll
            for (int mt = 0; mt < 2; mt++) {
                int r = (wm * 32 + mt * 16 + g) * PST + ks + 2 * tq;
                ah[mt][0] = *(const uint32_t*)&Ph[r];
                ah[mt][1] = *(const uint32_t*)&Ph[r + 8 * PST];
                ah[mt][2] = *(const uint32_t*)&Ph[r + 8];
                ah[mt][3] = *(const uint32_t*)&Ph[r + 8 * PST + 8];
                al[mt][0] = *(const uint32_t*)&Pl[r];
                al[mt][1] = *(const uint32_t*)&Pl[r + 8 * PST];
                al[mt][2] = *(const uint32_t*)&Pl[r + 8];
                al[mt][3] = *(const uint32_t*)&Pl[r + 8 * PST + 8];
            }
            uint32_t bh[4][2], bl[4][2];
            #pragma unroll
            for (int nt = 0; nt < 4; nt++) {
                int r = (wn * 32 + nt * 8 + g) * PST + ks + 2 * tq;
                bh[nt][0] = *(const uint32_t*)&Vh[r];
                bh[nt][1] = *(const uint32_t*)&Vh[r + 8];
                bl[nt][0] = *(const uint32_t*)&Vl[r];
                bl[nt][1] = *(const uint32_t*)&Vl[r + 8];
            }
            #pragma unroll
            for (int mt = 0; mt < 2; mt++)
                #pragma unroll
                for (int nt = 0; nt < 4; nt++) {
                    MMA_OP(acc[mt][nt], ah[mt], bh[nt]);
                    MMA_OP(acc[mt][nt], ah[mt], bl[nt]);
                    MMA_OP(acc[mt][nt], al[mt], bh[nt]);
                }
        }
    };

    LOADG(0);
    STORES(0);
    __syncthreads();
    const int NKT = SEQ / 32;
    for (int kt_i = 0; kt_i < NKT; kt_i++) {
        if (kt_i + 1 < NKT) LOADG((kt_i + 1) * 32);
        COMPUTE(kt_i & 1);
        if (kt_i + 1 < NKT) STORES((kt_i & 1) ^ 1);
        __syncthreads();
    }

    #pragma unroll
    for (int mt = 0; mt < 2; mt++)
        #pragma unroll
        for (int nt = 0; nt < 4; nt++) {
            int qq = q0 + wm * 32 + mt * 16 + g;
            int dd = wn * 32 + nt * 8 + 2 * tq;
            *(float2*)&out[(b * SEQ + qq) * DMODEL + dd] =
                make_float2(acc[mt][nt][0], acc[mt][nt][1]);
            *(float2*)&out[(b * SEQ + qq + 8) * DMODEL + dd] =
                make_float2(acc[mt][nt][2], acc[mt][nt][3]);
        }
}

// ============================================================
extern "C" void kernel_launch(void* const* d_in, const int* in_sizes, int n_in,
                              void* d_out, int out_size)
{
    const float* queries = (const float*)d_in[0];
    const float* keys    = (const float*)d_in[1];
    const float* values  = (const float*)d_in[2];
    const int*   vlens   = (const int*)  d_in[3];
    const float* Wql     = (const float*)d_in[4];
    const float* bql     = (const float*)d_in[5];
    const float* Wkl     = (const float*)d_in[6];
    const float* bkl     = (const float*)d_in[7];
    const float* Wqh     = (const float*)d_in[8];
    const float* bqh     = (const float*)d_in[9];
    const float* Wkh     = (const float*)d_in[10];
    const float* bkh     = (const float*)d_in[11];
    float* out = (float*)d_out;

    static bool attr_set = false;
    if (!attr_set) {
        cudaFuncSetAttribute(out_gemm_mma,
                             cudaFuncAttributeMaxDynamicSharedMemorySize, MMA_SMEM);
        attr_set = true;
    }

    zero_kernel<<<BATCH * SEQ / 256, 256>>>();
    proj_kernel<<<BATCH * SEQ, 64>>>(queries, keys, Wql, bql, Wkl, bkl,
                                     Wqh, bqh, Wkh, bkh);
    scores_kernel<<<dim3(SEQ / 128, SEQ / 64, BATCH), 256>>>(vlens);
    topk_kernel<<<dim3(SEQ, BATCH), 256>>>();
    finalize_kernel<<<BATCH * SEQ / 256, 256>>>();
    vconv_kernel<<<dim3(SEQ / 32, BATCH), 256>>>(values);
    out_gemm_mma<<<dim3(SEQ / 64, BATCH), 256, MMA_SMEM>>>(out);
}

// round 11
// speedup vs baseline: 2.0984x; 1.1674x over previous
#include <cuda_runtime.h>
#include <cuda_bf16.h>
#include <cstdint>
#include <cfloat>

#define BATCH 4
#define SEQ   2048
#define DMODEL 128
#define DLOW  16
#define NEGV  (-1e9f)
#define SCALE 0.25f
#define NQB   32

// ---- scratch (static __device__, no allocations) ----
__device__ float g_S[BATCH * SEQ * SEQ];          // 64 MB: exp(corrected scores)
__device__ float g_qlow[BATCH * SEQ * DLOW];
__device__ float g_klowT[BATCH * DLOW * SEQ];
__device__ float g_c[BATCH * SEQ];                // exp(correction score)
__device__ float g_w[BATCH * SEQ];                // 1 / column Z
__device__ float g_part[NQB][BATCH * SEQ];
__device__ float g_Zadj[BATCH * SEQ];
__device__ __nv_bfloat16 g_VhT[BATCH * DMODEL * SEQ];   // (V*w)^T hi, [b][d][k]
__device__ __nv_bfloat16 g_VlT[BATCH * DMODEL * SEQ];   // (V*w)^T lo

// ============================================================
__global__ void zero_kernel()
{
    g_Zadj[blockIdx.x * 256 + threadIdx.x] = 0.f;
}

// ============================================================
// K1: projections. One block (64 threads) per (b, position).
// ============================================================
__global__ void proj_kernel(const float* __restrict__ q, const float* __restrict__ k,
                            const float* __restrict__ Wql, const float* __restrict__ bql,
                            const float* __restrict__ Wkl, const float* __restrict__ bkl,
                            const float* __restrict__ Wqh, const float* __restrict__ bqh,
                            const float* __restrict__ Wkh, const float* __restrict__ bkh)
{
    int p = blockIdx.x;
    int b = p >> 11, i = p & (SEQ - 1);
    __shared__ float qs[DMODEL], ks[DMODEL];
    __shared__ float qh[DLOW], kh[DLOW];
    int t = threadIdx.x;
    {
        float2 qv = *(const float2*)&q[p * DMODEL + t * 2];
        qs[t * 2] = qv.x; qs[t * 2 + 1] = qv.y;
        float2 kv = *(const float2*)&k[p * DMODEL + t * 2];
        ks[t * 2] = kv.x; ks[t * 2 + 1] = kv.y;
    }
    __syncthreads();
    int j = t & 15;
    int which = t >> 4;
    const float* W; const float* bias; const float* src;
    if (which == 0)      { W = Wql; bias = bql; src = qs; }
    else if (which == 1) { W = Wkl; bias = bkl; src = ks; }
    else if (which == 2) { W = Wqh; bias = bqh; src = qs; }
    else                 { W = Wkh; bias = bkh; src = ks; }
    float acc = bias[j];
    #pragma unroll 16
    for (int d0 = 0; d0 < DMODEL; d0++)
        acc = fmaf(src[d0], W[d0 * DLOW + j], acc);
    if (which == 0)      g_qlow[p * DLOW + j] = acc;
    else if (which == 1) g_klowT[(b * DLOW + j) * SEQ + i] = acc;
    else if (which == 2) qh[j] = acc;
    else                 kh[j] = acc;
    __syncthreads();
    if (t == 0) {
        float c = 0.f;
        #pragma unroll
        for (int jj = 0; jj < DLOW; jj++) c = fmaf(qh[jj], kh[jj], c);
        g_c[p] = __expf(c * SCALE);
    }
}

// ============================================================
// K2a: exp(masked low-rank scores) + column partial sums.
// ============================================================
__global__ void scores_kernel(const int* __restrict__ valid_lens)
{
    int b  = blockIdx.z;
    int q0 = blockIdx.y * 64;
    int k0 = blockIdx.x * 128;
    __shared__ float qT[DLOW][64];
    __shared__ float kS[DLOW][128];
    __shared__ float redsm[8][128];
    int t = threadIdx.x;
    {
        int row = t >> 2, j0 = (t & 3) * 4;
        const float4 v = *(const float4*)&g_qlow[(b * SEQ + q0 + row) * DLOW + j0];
        qT[j0 + 0][row] = v.x; qT[j0 + 1][row] = v.y;
        qT[j0 + 2][row] = v.z; qT[j0 + 3][row] = v.w;
    }
    {
        int row = t >> 5, c0 = (t & 31) * 4;
        #pragma unroll
        for (int r = 0; r < DLOW; r += 8)
            *(float4*)&kS[row + r][c0] =
                *(const float4*)&g_klowT[(b * DLOW + row + r) * SEQ + k0 + c0];
    }
    __syncthreads();
    int tx = t & 31, ty = t >> 5;
    int m0 = ty * 8, n0 = tx * 4;
    float acc[8][4];
    #pragma unroll
    for (int i = 0; i < 8; i++)
        #pragma unroll
        for (int jj = 0; jj < 4; jj++) acc[i][jj] = 0.f;
    #pragma unroll
    for (int j = 0; j < DLOW; j++) {
        float a[8];
        *(float4*)&a[0] = *(const float4*)&qT[j][m0];
        *(float4*)&a[4] = *(const float4*)&qT[j][m0 + 4];
        float4 bv = *(const float4*)&kS[j][n0];
        #pragma unroll
        for (int i = 0; i < 8; i++) {
            acc[i][0] = fmaf(a[i], bv.x, acc[i][0]);
            acc[i][1] = fmaf(a[i], bv.y, acc[i][1]);
            acc[i][2] = fmaf(a[i], bv.z, acc[i][2]);
            acc[i][3] = fmaf(a[i], bv.w, acc[i][3]);
        }
    }
    int vl[4];
    #pragma unroll
    for (int jj = 0; jj < 4; jj++) {
        int v = valid_lens[b * SEQ + k0 + n0 + jj];
        vl[jj] = min(max(v, 0), SEQ - 1);
    }
    float cs[4] = {0.f, 0.f, 0.f, 0.f};
    #pragma unroll
    for (int i = 0; i < 8; i++) {
        int qrow = q0 + m0 + i;
        float4 o; float* po = (float*)&o;
        #pragma unroll
        for (int jj = 0; jj < 4; jj++) {
            float v = acc[i][jj] * SCALE;
            if (vl[jj] == qrow) v += NEGV;
            float e = __expf(v);
            po[jj] = e;
            cs[jj] += e;
        }
        *(float4*)&g_S[(b * SEQ + qrow) * SEQ + k0 + n0] = o;
    }
    #pragma unroll
    for (int jj = 0; jj < 4; jj++) redsm[ty][n0 + jj] = cs[jj];
    __syncthreads();
    if (t < 128) {
        float s = 0.f;
        #pragma unroll
        for (int r = 0; r < 8; r++) s += redsm[r][t];
        g_part[blockIdx.y][b * SEQ + k0 + t] = s;
    }
}

// ============================================================
// K2b: warp-per-row exact threshold top-8. No block syncs.
// Pass 1: lane maxes -> T = 8th largest of 32 lane-maxes (exact bound).
// Pass 2: compact candidates >= T (L1-resident re-read) -> 64-slot list.
// 8 argmax iterations over the list; lane 0 scatters exp(c) + Zadj.
// Fallback (list overflow, ~never): exact global rescan.
// ============================================================
__global__ void __launch_bounds__(256) topk_kernel()
{
    __shared__ float cV[8][64];
    __shared__ int   cI[8][64];
    __shared__ int   cnt[8];
    int t = threadIdx.x, lane = t & 31, w = t >> 5;
    int row = blockIdx.x * 8 + w;                 // 0..8191
    int b = row >> 11;
    float* Srow = &g_S[row * SEQ];

    // ---- pass 1: lane max over strided chunks ----
    float lm = -FLT_MAX;
    #pragma unroll
    for (int it = 0; it < 16; it++) {
        float4 x = *(const float4*)&Srow[it * 128 + lane * 4];
        lm = fmaxf(lm, fmaxf(fmaxf(x.x, x.y), fmaxf(x.z, x.w)));
    }
    // T = 8th largest of the 32 lane maxes
    float a = lm, T = lm;
    #pragma unroll
    for (int it = 0; it < 8; it++) {
        float m = a;
        #pragma unroll
        for (int off = 16; off > 0; off >>= 1)
            m = fmaxf(m, __shfl_xor_sync(0xffffffffu, m, off));
        T = m;
        unsigned ba = __ballot_sync(0xffffffffu, a == m);
        if (lane == (int)(__ffs(ba) - 1)) a = -FLT_MAX;
    }

    // ---- pass 2: compact candidates >= T ----
    if (lane == 0) cnt[w] = 0;
    __syncwarp();
    #pragma unroll
    for (int it = 0; it < 16; it++) {
        float4 x = *(const float4*)&Srow[it * 128 + lane * 4];
        const float* xv = (const float*)&x;
        #pragma unroll
        for (int jj = 0; jj < 4; jj++) {
            if (xv[jj] >= T) {
                int p = atomicAdd(&cnt[w], 1);
                if (p < 64) { cV[w][p] = xv[jj]; cI[w][p] = it * 128 + lane * 4 + jj; }
            }
        }
    }
    __syncwarp();
    int nc = cnt[w];

    int   chI[8];
    float chV[8];

    if (nc <= 64) {
        // fast path: top-8 over the candidate list
        #pragma unroll 1
        for (int it = 0; it < 8; it++) {
            float bv = -FLT_MAX; int bi = 0x7fffffff;
            for (int p = lane; p < nc; p += 32) {
                float cv = cV[w][p]; int ci = cI[w][p];
                if (cv > bv || (cv == bv && ci < bi)) { bv = cv; bi = ci; }
            }
            #pragma unroll
            for (int off = 16; off > 0; off >>= 1) {
                float ov = __shfl_xor_sync(0xffffffffu, bv, off);
                int   oi = __shfl_xor_sync(0xffffffffu, bi, off);
                if (ov > bv || (ov == bv && oi < bi)) { bv = ov; bi = oi; }
            }
            for (int p = lane; p < nc; p += 32)
                if (cI[w][p] == bi) cV[w][p] = -FLT_MAX;
            chI[it] = bi; chV[it] = bv;
        }
    } else {
        // exact slow path: iterative argmax with chosen-exclusion (global rescan)
        #pragma unroll 1
        for (int it = 0; it < 8; it++) {
            float bv = -FLT_MAX; int bi = 0x7fffffff;
            for (int p = lane; p < SEQ; p += 32) {
                bool skip = false;
                #pragma unroll 8
                for (int x = 0; x < 8; x++)
                    if (x < it && chI[x] == p) skip = true;
                if (skip) continue;
                float cv = Srow[p];
                if (cv > bv || (cv == bv && p < bi)) { bv = cv; bi = p; }
            }
            #pragma unroll
            for (int off = 16; off > 0; off >>= 1) {
                float ov = __shfl_xor_sync(0xffffffffu, bv, off);
                int   oi = __shfl_xor_sync(0xffffffffu, bi, off);
                if (ov > bv || (ov == bv && oi < bi)) { bv = ov; bi = oi; }
            }
            chI[it] = bi; chV[it] = bv;
        }
    }

    if (lane == 0) {
        #pragma unroll
        for (int it = 0; it < 8; it++) {
            int bi = chI[it];
            float ec = g_c[b * SEQ + bi];
            Srow[bi] = ec;
            atomicAdd(&g_Zadj[b * SEQ + bi], ec - chV[it]);
        }
    }
}

// ============================================================
// K3: w = 1 / (sum of partials + scatter corrections)
// ============================================================
__global__ void finalize_kernel()
{
    int i = blockIdx.x * 256 + threadIdx.x;
    float z = g_Zadj[i];
    #pragma unroll
    for (int s = 0; s < NQB; s++) z += g_part[s][i];
    g_w[i] = 1.0f / z;
}

// ============================================================
// K3b: (V*w)^T split into bf16 hi/lo, [b][d][k] layout.
// ============================================================
__global__ void vconv_kernel(const float* __restrict__ V)
{
    int b = blockIdx.y, k0 = blockIdx.x * 32;
    __shared__ float vs[32][129];
    int t = threadIdx.x;
    {
        int r = t >> 3, c0 = (t & 7) * 16;
        float wk = g_w[b * SEQ + k0 + r];
        #pragma unroll
        for (int qd = 0; qd < 4; qd++) {
            float4 vv = *(const float4*)&V[(b * SEQ + k0 + r) * DMODEL + c0 + qd * 4];
            vs[r][c0 + qd * 4 + 0] = vv.x * wk;
            vs[r][c0 + qd * 4 + 1] = vv.y * wk;
            vs[r][c0 + qd * 4 + 2] = vv.z * wk;
            vs[r][c0 + qd * 4 + 3] = vv.w * wk;
        }
    }
    __syncthreads();
    int d = t >> 1, kh = (t & 1) * 16;
    uint4 hq[2], lq[2];
    __nv_bfloat162* hp = (__nv_bfloat162*)hq;
    __nv_bfloat162* lp = (__nv_bfloat162*)lq;
    #pragma unroll
    for (int i = 0; i < 8; i++) {
        float x0 = vs[kh + 2 * i][d], x1 = vs[kh + 2 * i + 1][d];
        __nv_bfloat16 h0 = __float2bfloat16(x0), h1 = __float2bfloat16(x1);
        hp[i] = __halves2bfloat162(h0, h1);
        lp[i] = __halves2bfloat162(__float2bfloat16(x0 - __bfloat162float(h0)),
                                   __float2bfloat16(x1 - __bfloat162float(h1)));
    }
    __nv_bfloat16* dsth = &g_VhT[(b * DMODEL + d) * SEQ + k0 + kh];
    *(uint4*)dsth = hq[0];
    *((uint4*)dsth + 1) = hq[1];
    __nv_bfloat16* dstl = &g_VlT[(b * DMODEL + d) * SEQ + k0 + kh];
    *(uint4*)dstl = lq[0];
    *((uint4*)dstl + 1) = lq[1];
}

// ============================================================
// K4: tensor-core output GEMM with split-bf16 compensation.
// ============================================================
#define PST   40
#define P_SZ  (64 * PST)
#define V_SZ  (128 * PST)
#define BUFE  (2 * P_SZ + 2 * V_SZ)
#define MMA_SMEM (2 * BUFE * 2)

#define MMA_OP(c, a, bb) \
    asm volatile("mma.sync.aligned.m16n8k16.row.col.f32.bf16.bf16.f32 " \
        "{%0,%1,%2,%3}, {%4,%5,%6,%7}, {%8,%9}, {%0,%1,%2,%3};" \
        : "+f"((c)[0]), "+f"((c)[1]), "+f"((c)[2]), "+f"((c)[3]) \
        : "r"((a)[0]), "r"((a)[1]), "r"((a)[2]), "r"((a)[3]), \
          "r"((bb)[0]), "r"((bb)[1]))

__global__ void __launch_bounds__(256) out_gemm_mma(float* __restrict__ out)
{
    extern __shared__ __nv_bfloat16 smb[];
    int b = blockIdx.y, q0 = blockIdx.x * 64;
    int t = threadIdx.x, lane = t & 31, w = t >> 5;
    int g = lane >> 2, tq = lane & 3;
    int wm = w >> 2, wn = w & 3;

    const float* Sbase = &g_S[(b * SEQ + q0) * SEQ];
    const __nv_bfloat16* VhB = &g_VhT[b * DMODEL * SEQ];
    const __nv_bfloat16* VlB = &g_VlT[b * DMODEL * SEQ];

    int s_q = t >> 2, s_k = (t & 3) * 8;
    int v_d = t >> 1, v_k = (t & 1) * 16;

    float acc[2][4][4];
    #pragma unroll
    for (int mt = 0; mt < 2; mt++)
        #pragma unroll
        for (int nt = 0; nt < 4; nt++)
            #pragma unroll
            for (int x = 0; x < 4; x++) acc[mt][nt][x] = 0.f;

    float4 sP[2]; uint4 sVh[2], sVl[2];

    auto LOADG = [&](int kt) {
        sP[0] = *(const float4*)&Sbase[s_q * SEQ + kt + s_k];
        sP[1] = *(const float4*)&Sbase[s_q * SEQ + kt + s_k + 4];
        const uint4* ph = (const uint4*)&VhB[v_d * SEQ + kt + v_k];
        sVh[0] = ph[0]; sVh[1] = ph[1];
        const uint4* pl = (const uint4*)&VlB[v_d * SEQ + kt + v_k];
        sVl[0] = pl[0]; sVl[1] = pl[1];
    };
    auto STORES = [&](int buf) {
        __nv_bfloat16* Ph = smb + buf * BUFE;
        __nv_bfloat16* Pl = Ph + P_SZ;
        __nv_bfloat16* Vh = Ph + 2 * P_SZ;
        __nv_bfloat16* Vl = Vh + V_SZ;
        float f[8];
        *(float4*)&f[0] = sP[0]; *(float4*)&f[4] = sP[1];
        uint4 hq, lq;
        __nv_bfloat162* hp = (__nv_bfloat162*)&hq;
        __nv_bfloat162* lp = (__nv_bfloat162*)&lq;
        #pragma unroll
        for (int i = 0; i < 4; i++) {
            __nv_bfloat16 h0 = __float2bfloat16(f[2 * i]);
            __nv_bfloat16 h1 = __float2bfloat16(f[2 * i + 1]);
            hp[i] = __halves2bfloat162(h0, h1);
            lp[i] = __halves2bfloat162(
                __float2bfloat16(f[2 * i] - __bfloat162float(h0)),
                __float2bfloat16(f[2 * i + 1] - __bfloat162float(h1)));
        }
        *(uint4*)&Ph[s_q * PST + s_k] = hq;
        *(uint4*)&Pl[s_q * PST + s_k] = lq;
        *(uint4*)&Vh[v_d * PST + v_k]     = sVh[0];
        *(uint4*)&Vh[v_d * PST + v_k + 8] = sVh[1];
        *(uint4*)&Vl[v_d * PST + v_k]     = sVl[0];
        *(uint4*)&Vl[v_d * PST + v_k + 8] = sVl[1];
    };
    auto COMPUTE = [&](int buf) {
        const __nv_bfloat16* Ph = smb + buf * BUFE;
        const __nv_bfloat16* Pl = Ph + P_SZ;
        const __nv_bfloat16* Vh = Ph + 2 * P_SZ;
        const __nv_bfloat16* Vl = Vh + V_SZ;
        #pragma unroll
        for (int ks = 0; ks < 32; ks += 16) {
            uint32_t ah[2][4], al[2][4];
            #pragma unroll
            for (int mt = 0; mt < 2; mt++) {
                int r = (wm * 32 + mt * 16 + g) * PST + ks + 2 * tq;
                ah[mt][0] = *(const uint32_t*)&Ph[r];
                ah[mt][1] = *(const uint32_t*)&Ph[r + 8 * PST];
                ah[mt][2] = *(const uint32_t*)&Ph[r + 8];
                ah[mt][3] = *(const uint32_t*)&Ph[r + 8 * PST + 8];
                al[mt][0] = *(const uint32_t*)&Pl[r];
                al[mt][1] = *(const uint32_t*)&Pl[r + 8 * PST];
                al[mt][2] = *(const uint32_t*)&Pl[r + 8];
                al[mt][3] = *(const uint32_t*)&Pl[r + 8 * PST + 8];
            }
            uint32_t bh[4][2], bl[4][2];
            #pragma unroll
            for (int nt = 0; nt < 4; nt++) {
                int r = (wn * 32 + nt * 8 + g) * PST + ks + 2 * tq;
                bh[nt][0] = *(const uint32_t*)&Vh[r];
                bh[nt][1] = *(const uint32_t*)&Vh[r + 8];
                bl[nt][0] = *(const uint32_t*)&Vl[r];
                bl[nt][1] = *(const uint32_t*)&Vl[r + 8];
            }
            #pragma unroll
            for (int mt = 0; mt < 2; mt++)
                #pragma unroll
                for (int nt = 0; nt < 4; nt++) {
                    MMA_OP(acc[mt][nt], ah[mt], bh[nt]);
                    MMA_OP(acc[mt][nt], ah[mt], bl[nt]);
                    MMA_OP(acc[mt][nt], al[mt], bh[nt]);
                }
        }
    };

    LOADG(0);
    STORES(0);
    __syncthreads();
    const int NKT = SEQ / 32;
    for (int kt_i = 0; kt_i < NKT; kt_i++) {
        if (kt_i + 1 < NKT) LOADG((kt_i + 1) * 32);
        COMPUTE(kt_i & 1);
        if (kt_i + 1 < NKT) STORES((kt_i & 1) ^ 1);
        __syncthreads();
    }

    #pragma unroll
    for (int mt = 0; mt < 2; mt++)
        #pragma unroll
        for (int nt = 0; nt < 4; nt++) {
            int qq = q0 + wm * 32 + mt * 16 + g;
            int dd = wn * 32 + nt * 8 + 2 * tq;
            *(float2*)&out[(b * SEQ + qq) * DMODEL + dd] =
                make_float2(acc[mt][nt][0], acc[mt][nt][1]);
            *(float2*)&out[(b * SEQ + qq + 8) * DMODEL + dd] =
                make_float2(acc[mt][nt][2], acc[mt][nt][3]);
        }
}

// ============================================================
extern "C" void kernel_launch(void* const* d_in, const int* in_sizes, int n_in,
                              void* d_out, int out_size)
{
    const float* queries = (const float*)d_in[0];
    const float* keys    = (const float*)d_in[1];
    const float* values  = (const float*)d_in[2];
    const int*   vlens   = (const int*)  d_in[3];
    const float* Wql     = (const float*)d_in[4];
    const float* bql     = (const float*)d_in[5];
    const float* Wkl     = (const float*)d_in[6];
    const float* bkl     = (const float*)d_in[7];
    const float* Wqh     = (const float*)d_in[8];
    const float* bqh     = (const float*)d_in[9];
    const float* Wkh     = (const float*)d_in[10];
    const float* bkh     = (const float*)d_in[11];
    float* out = (float*)d_out;

    static bool attr_set = false;
    if (!attr_set) {
        cudaFuncSetAttribute(out_gemm_mma,
                             cudaFuncAttributeMaxDynamicSharedMemorySize, MMA_SMEM);
        attr_set = true;
    }

    zero_kernel<<<BATCH * SEQ / 256, 256>>>();
    proj_kernel<<<BATCH * SEQ, 64>>>(queries, keys, Wql, bql, Wkl, bkl,
                                     Wqh, bqh, Wkh, bkh);
    scores_kernel<<<dim3(SEQ / 128, SEQ / 64, BATCH), 256>>>(vlens);
    topk_kernel<<<BATCH * SEQ / 8, 256>>>();
    finalize_kernel<<<BATCH * SEQ / 256, 256>>>();
    vconv_kernel<<<dim3(SEQ / 32, BATCH), 256>>>(values);
    out_gemm_mma<<<dim3(SEQ / 64, BATCH), 256, MMA_SMEM>>>(out);
}

// round 12
// speedup vs baseline: 2.1280x; 1.0141x over previous
#include <cuda_runtime.h>
#include <cuda_bf16.h>
#include <cstdint>
#include <cfloat>

#define BATCH 4
#define SEQ   2048
#define DMODEL 128
#define DLOW  16
#define NEGV  (-1e9f)
#define SCALE 0.25f
#define NQB   32

// ---- scratch (static __device__, no allocations) ----
__device__ float g_S[BATCH * SEQ * SEQ];          // 64 MB: exp(corrected scores)
__device__ float g_qlow[BATCH * SEQ * DLOW];
__device__ float g_klowT[BATCH * DLOW * SEQ];
__device__ float g_c[BATCH * SEQ];                // exp(correction score)
__device__ float g_part[NQB][BATCH * SEQ];
__device__ float g_Zadj[BATCH * SEQ];
__device__ float g_cmax[BATCH * SEQ * 16];        // per-row per-128-chunk maxima
__device__ __nv_bfloat16 g_VhT[BATCH * DMODEL * SEQ];   // (V*w)^T hi, [b][d][k]
__device__ __nv_bfloat16 g_VlT[BATCH * DMODEL * SEQ];   // (V*w)^T lo

// ============================================================
__global__ void zero_kernel()
{
    g_Zadj[blockIdx.x * 256 + threadIdx.x] = 0.f;
}

// ============================================================
// K1: projections. One block (64 threads) per (b, position).
// ============================================================
__global__ void proj_kernel(const float* __restrict__ q, const float* __restrict__ k,
                            const float* __restrict__ Wql, const float* __restrict__ bql,
                            const float* __restrict__ Wkl, const float* __restrict__ bkl,
                            const float* __restrict__ Wqh, const float* __restrict__ bqh,
                            const float* __restrict__ Wkh, const float* __restrict__ bkh)
{
    int p = blockIdx.x;
    int b = p >> 11, i = p & (SEQ - 1);
    __shared__ float qs[DMODEL], ks[DMODEL];
    __shared__ float qh[DLOW], kh[DLOW];
    int t = threadIdx.x;
    {
        float2 qv = *(const float2*)&q[p * DMODEL + t * 2];
        qs[t * 2] = qv.x; qs[t * 2 + 1] = qv.y;
        float2 kv = *(const float2*)&k[p * DMODEL + t * 2];
        ks[t * 2] = kv.x; ks[t * 2 + 1] = kv.y;
    }
    __syncthreads();
    int j = t & 15;
    int which = t >> 4;
    const float* W; const float* bias; const float* src;
    if (which == 0)      { W = Wql; bias = bql; src = qs; }
    else if (which == 1) { W = Wkl; bias = bkl; src = ks; }
    else if (which == 2) { W = Wqh; bias = bqh; src = qs; }
    else                 { W = Wkh; bias = bkh; src = ks; }
    float acc = bias[j];
    #pragma unroll 16
    for (int d0 = 0; d0 < DMODEL; d0++)
        acc = fmaf(src[d0], W[d0 * DLOW + j], acc);
    if (which == 0)      g_qlow[p * DLOW + j] = acc;
    else if (which == 1) g_klowT[(b * DLOW + j) * SEQ + i] = acc;
    else if (which == 2) qh[j] = acc;
    else                 kh[j] = acc;
    __syncthreads();
    if (t == 0) {
        float c = 0.f;
        #pragma unroll
        for (int jj = 0; jj < DLOW; jj++) c = fmaf(qh[jj], kh[jj], c);
        g_c[p] = __expf(c * SCALE);
    }
}

// ============================================================
// K2a: exp(masked low-rank scores) + column partial sums
//      + per-row chunk maxima (for single-pass top-k threshold).
// ============================================================
__global__ void scores_kernel(const int* __restrict__ valid_lens)
{
    int b  = blockIdx.z;
    int q0 = blockIdx.y * 64;
    int k0 = blockIdx.x * 128;
    __shared__ float qT[DLOW][64];
    __shared__ float kS[DLOW][128];
    __shared__ float redsm[8][128];
    int t = threadIdx.x;
    {
        int row = t >> 2, j0 = (t & 3) * 4;
        const float4 v = *(const float4*)&g_qlow[(b * SEQ + q0 + row) * DLOW + j0];
        qT[j0 + 0][row] = v.x; qT[j0 + 1][row] = v.y;
        qT[j0 + 2][row] = v.z; qT[j0 + 3][row] = v.w;
    }
    {
        int row = t >> 5, c0 = (t & 31) * 4;
        #pragma unroll
        for (int r = 0; r < DLOW; r += 8)
            *(float4*)&kS[row + r][c0] =
                *(const float4*)&g_klowT[(b * DLOW + row + r) * SEQ + k0 + c0];
    }
    __syncthreads();
    int tx = t & 31, ty = t >> 5;
    int m0 = ty * 8, n0 = tx * 4;
    float acc[8][4];
    #pragma unroll
    for (int i = 0; i < 8; i++)
        #pragma unroll
        for (int jj = 0; jj < 4; jj++) acc[i][jj] = 0.f;
    #pragma unroll
    for (int j = 0; j < DLOW; j++) {
        float a[8];
        *(float4*)&a[0] = *(const float4*)&qT[j][m0];
        *(float4*)&a[4] = *(const float4*)&qT[j][m0 + 4];
        float4 bv = *(const float4*)&kS[j][n0];
        #pragma unroll
        for (int i = 0; i < 8; i++) {
            acc[i][0] = fmaf(a[i], bv.x, acc[i][0]);
            acc[i][1] = fmaf(a[i], bv.y, acc[i][1]);
            acc[i][2] = fmaf(a[i], bv.z, acc[i][2]);
            acc[i][3] = fmaf(a[i], bv.w, acc[i][3]);
        }
    }
    int vl[4];
    #pragma unroll
    for (int jj = 0; jj < 4; jj++) {
        int v = valid_lens[b * SEQ + k0 + n0 + jj];
        vl[jj] = min(max(v, 0), SEQ - 1);
    }
    float cs[4] = {0.f, 0.f, 0.f, 0.f};
    float rmax[8];
    #pragma unroll
    for (int i = 0; i < 8; i++) {
        int qrow = q0 + m0 + i;
        float4 o; float* po = (float*)&o;
        float rm = -FLT_MAX;
        #pragma unroll
        for (int jj = 0; jj < 4; jj++) {
            float v = acc[i][jj] * SCALE;
            if (vl[jj] == qrow) v += NEGV;
            float e = __expf(v);
            po[jj] = e;
            cs[jj] += e;
            rm = fmaxf(rm, e);
        }
        rmax[i] = rm;
        *(float4*)&g_S[(b * SEQ + qrow) * SEQ + k0 + n0] = o;
    }
    // per-row chunk maxima: reduce across the 32 lanes of this warp (one row each i)
    #pragma unroll
    for (int i = 0; i < 8; i++) {
        float rm = rmax[i];
        #pragma unroll
        for (int off = 16; off > 0; off >>= 1)
            rm = fmaxf(rm, __shfl_xor_sync(0xffffffffu, rm, off));
        if (tx == 0)
            g_cmax[(b * SEQ + q0 + m0 + i) * 16 + blockIdx.x] = rm;
    }
    #pragma unroll
    for (int jj = 0; jj < 4; jj++) redsm[ty][n0 + jj] = cs[jj];
    __syncthreads();
    if (t < 128) {
        float s = 0.f;
        #pragma unroll
        for (int r = 0; r < 8; r++) s += redsm[r][t];
        g_part[blockIdx.y][b * SEQ + k0 + t] = s;
    }
}

// ============================================================
// K2b: warp-per-row exact threshold top-8, SINGLE streaming pass.
// T = 8th largest of the 16 precomputed chunk maxima (exact bound:
// 8 distinct chunks each hold an element >= T; every top-8 elem >= T).
// Collect candidates >= T into 64-slot list; exact fallback on overflow.
// ============================================================
__global__ void __launch_bounds__(256) topk_kernel()
{
    __shared__ float cV[8][64];
    __shared__ int   cI[8][64];
    __shared__ int   cnt[8];
    int t = threadIdx.x, lane = t & 31, w = t >> 5;
    int row = blockIdx.x * 8 + w;                 // 0..8191
    int b = row >> 11;
    float* Srow = &g_S[row * SEQ];

    // threshold from precomputed chunk maxima
    float a = (lane < 16) ? g_cmax[row * 16 + lane] : -FLT_MAX;
    float T = a;
    #pragma unroll
    for (int it = 0; it < 8; it++) {
        float m = a;
        #pragma unroll
        for (int off = 16; off > 0; off >>= 1)
            m = fmaxf(m, __shfl_xor_sync(0xffffffffu, m, off));
        T = m;
        unsigned ba = __ballot_sync(0xffffffffu, a == m);
        if (lane == (int)(__ffs(ba) - 1)) a = -FLT_MAX;
    }

    // single pass: collect candidates >= T
    if (lane == 0) cnt[w] = 0;
    __syncwarp();
    #pragma unroll
    for (int it = 0; it < 16; it++) {
        float4 x = *(const float4*)&Srow[it * 128 + lane * 4];
        const float* xv = (const float*)&x;
        #pragma unroll
        for (int jj = 0; jj < 4; jj++) {
            if (xv[jj] >= T) {
                int p = atomicAdd(&cnt[w], 1);
                if (p < 64) { cV[w][p] = xv[jj]; cI[w][p] = it * 128 + lane * 4 + jj; }
            }
        }
    }
    __syncwarp();
    int nc = cnt[w];

    int   chI[8];
    float chV[8];

    if (nc <= 64) {
        #pragma unroll 1
        for (int it = 0; it < 8; it++) {
            float bv = -FLT_MAX; int bi = 0x7fffffff;
            for (int p = lane; p < nc; p += 32) {
                float cv = cV[w][p]; int ci = cI[w][p];
                if (cv > bv || (cv == bv && ci < bi)) { bv = cv; bi = ci; }
            }
            #pragma unroll
            for (int off = 16; off > 0; off >>= 1) {
                float ov = __shfl_xor_sync(0xffffffffu, bv, off);
                int   oi = __shfl_xor_sync(0xffffffffu, bi, off);
                if (ov > bv || (ov == bv && oi < bi)) { bv = ov; bi = oi; }
            }
            for (int p = lane; p < nc; p += 32)
                if (cI[w][p] == bi) cV[w][p] = -FLT_MAX;
            chI[it] = bi; chV[it] = bv;
        }
    } else {
        // exact slow path: iterative argmax with chosen-exclusion (global rescan)
        #pragma unroll 1
        for (int it = 0; it < 8; it++) {
            float bv = -FLT_MAX; int bi = 0x7fffffff;
            for (int p = lane; p < SEQ; p += 32) {
                bool skip = false;
                #pragma unroll 8
                for (int x = 0; x < 8; x++)
                    if (x < it && chI[x] == p) skip = true;
                if (skip) continue;
                float cv = Srow[p];
                if (cv > bv || (cv == bv && p < bi)) { bv = cv; bi = p; }
            }
            #pragma unroll
            for (int off = 16; off > 0; off >>= 1) {
                float ov = __shfl_xor_sync(0xffffffffu, bv, off);
                int   oi = __shfl_xor_sync(0xffffffffu, bi, off);
                if (ov > bv || (ov == bv && oi < bi)) { bv = ov; bi = oi; }
            }
            chI[it] = bi; chV[it] = bv;
        }
    }

    if (lane == 0) {
        #pragma unroll
        for (int it = 0; it < 8; it++) {
            int bi = chI[it];
            float ec = g_c[b * SEQ + bi];
            Srow[bi] = ec;
            atomicAdd(&g_Zadj[b * SEQ + bi], ec - chV[it]);
        }
    }
}

// ============================================================
// K3: (V*w)^T split into bf16 hi/lo, [b][d][k]; finalize (w = 1/Z) fused.
// ============================================================
__global__ void vconv_kernel(const float* __restrict__ V)
{
    int b = blockIdx.y, k0 = blockIdx.x * 32;
    __shared__ float vs[32][129];
    __shared__ float wsh[32];
    int t = threadIdx.x;
    if (t < 32) {
        int idx = b * SEQ + k0 + t;
        float z = g_Zadj[idx];
        #pragma unroll
        for (int s = 0; s < NQB; s++) z += g_part[s][idx];
        wsh[t] = 1.0f / z;
    }
    __syncthreads();
    {
        int r = t >> 3, c0 = (t & 7) * 16;
        float wk = wsh[r];
        #pragma unroll
        for (int qd = 0; qd < 4; qd++) {
            float4 vv = *(const float4*)&V[(b * SEQ + k0 + r) * DMODEL + c0 + qd * 4];
            vs[r][c0 + qd * 4 + 0] = vv.x * wk;
            vs[r][c0 + qd * 4 + 1] = vv.y * wk;
            vs[r][c0 + qd * 4 + 2] = vv.z * wk;
            vs[r][c0 + qd * 4 + 3] = vv.w * wk;
        }
    }
    __syncthreads();
    int d = t >> 1, kh = (t & 1) * 16;
    uint4 hq[2], lq[2];
    __nv_bfloat162* hp = (__nv_bfloat162*)hq;
    __nv_bfloat162* lp = (__nv_bfloat162*)lq;
    #pragma unroll
    for (int i = 0; i < 8; i++) {
        float x0 = vs[kh + 2 * i][d], x1 = vs[kh + 2 * i + 1][d];
        __nv_bfloat16 h0 = __float2bfloat16(x0), h1 = __float2bfloat16(x1);
        hp[i] = __halves2bfloat162(h0, h1);
        lp[i] = __halves2bfloat162(__float2bfloat16(x0 - __bfloat162float(h0)),
                                   __float2bfloat16(x1 - __bfloat162float(h1)));
    }
    __nv_bfloat16* dsth = &g_VhT[(b * DMODEL + d) * SEQ + k0 + kh];
    *(uint4*)dsth = hq[0];
    *((uint4*)dsth + 1) = hq[1];
    __nv_bfloat16* dstl = &g_VlT[(b * DMODEL + d) * SEQ + k0 + kh];
    *(uint4*)dstl = lq[0];
    *((uint4*)dstl + 1) = lq[1];
}

// ============================================================
// K4: tensor-core output GEMM with split-bf16 compensation.
// ============================================================
#define PST   40
#define P_SZ  (64 * PST)
#define V_SZ  (128 * PST)
#define BUFE  (2 * P_SZ + 2 * V_SZ)
#define MMA_SMEM (2 * BUFE * 2)

#define MMA_OP(c, a, bb) \
    asm volatile("mma.sync.aligned.m16n8k16.row.col.f32.bf16.bf16.f32 " \
        "{%0,%1,%2,%3}, {%4,%5,%6,%7}, {%8,%9}, {%0,%1,%2,%3};" \
        : "+f"((c)[0]), "+f"((c)[1]), "+f"((c)[2]), "+f"((c)[3]) \
        : "r"((a)[0]), "r"((a)[1]), "r"((a)[2]), "r"((a)[3]), \
          "r"((bb)[0]), "r"((bb)[1]))

__global__ void __launch_bounds__(256) out_gemm_mma(float* __restrict__ out)
{
    extern __shared__ __nv_bfloat16 smb[];
    int b = blockIdx.y, q0 = blockIdx.x * 64;
    int t = threadIdx.x, lane = t & 31, w = t >> 5;
    int g = lane >> 2, tq = lane & 3;
    int wm = w >> 2, wn = w & 3;

    const float* Sbase = &g_S[(b * SEQ + q0) * SEQ];
    const __nv_bfloat16* VhB = &g_VhT[b * DMODEL * SEQ];
    const __nv_bfloat16* VlB = &g_VlT[b * DMODEL * SEQ];

    int s_q = t >> 2, s_k = (t & 3) * 8;
    int v_d = t >> 1, v_k = (t & 1) * 16;

    float acc[2][4][4];
    #pragma unroll
    for (int mt = 0; mt < 2; mt++)
        #pragma unroll
        for (int nt = 0; nt < 4; nt++)
            #pragma unroll
            for (int x = 0; x < 4; x++) acc[mt][nt][x] = 0.f;

    float4 sP[2]; uint4 sVh[2], sVl[2];

    auto LOADG = [&](int kt) {
        sP[0] = *(const float4*)&Sbase[s_q * SEQ + kt + s_k];
        sP[1] = *(const float4*)&Sbase[s_q * SEQ + kt + s_k + 4];
        const uint4* ph = (const uint4*)&VhB[v_d * SEQ + kt + v_k];
        sVh[0] = ph[0]; sVh[1] = ph[1];
        const uint4* pl = (const uint4*)&VlB[v_d * SEQ + kt + v_k];
        sVl[0] = pl[0]; sVl[1] = pl[1];
    };
    auto STORES = [&](int buf) {
        __nv_bfloat16* Ph = smb + buf * BUFE;
        __nv_bfloat16* Pl = Ph + P_SZ;
        __nv_bfloat16* Vh = Ph + 2 * P_SZ;
        __nv_bfloat16* Vl = Vh + V_SZ;
        float f[8];
        *(float4*)&f[0] = sP[0]; *(float4*)&f[4] = sP[1];
        uint4 hq, lq;
        __nv_bfloat162* hp = (__nv_bfloat162*)&hq;
        __nv_bfloat162* lp = (__nv_bfloat162*)&lq;
        #pragma unroll
        for (int i = 0; i < 4; i++) {
            __nv_bfloat16 h0 = __float2bfloat16(f[2 * i]);
            __nv_bfloat16 h1 = __float2bfloat16(f[2 * i + 1]);
            hp[i] = __halves2bfloat162(h0, h1);
            lp[i] = __halves2bfloat162(
                __float2bfloat16(f[2 * i] - __bfloat162float(h0)),
                __float2bfloat16(f[2 * i + 1] - __bfloat162float(h1)));
        }
        *(uint4*)&Ph[s_q * PST + s_k] = hq;
        *(uint4*)&Pl[s_q * PST + s_k] = lq;
        *(uint4*)&Vh[v_d * PST + v_k]     = sVh[0];
        *(uint4*)&Vh[v_d * PST + v_k + 8] = sVh[1];
        *(uint4*)&Vl[v_d * PST + v_k]     = sVl[0];
        *(uint4*)&Vl[v_d * PST + v_k + 8] = sVl[1];
    };
    auto COMPUTE = [&](int buf) {
        const __nv_bfloat16* Ph = smb + buf * BUFE;
        const __nv_bfloat16* Pl = Ph + P_SZ;
        const __nv_bfloat16* Vh = Ph + 2 * P_SZ;
        const __nv_bfloat16* Vl = Vh + V_SZ;
        #pragma unroll
        for (int ks = 0; ks < 32; ks += 16) {
            uint32_t ah[2][4], al[2][4];
            #pragma unroll
            for (int mt = 0; mt < 2; mt++) {
                int r = (wm * 32 + mt * 16 + g) * PST + ks + 2 * tq;
                ah[mt][0] = *(const uint32_t*)&Ph[r];
                ah[mt][1] = *(const uint32_t*)&Ph[r + 8 * PST];
                ah[mt][2] = *(const uint32_t*)&Ph[r + 8];
                ah[mt][3] = *(const uint32_t*)&Ph[r + 8 * PST + 8];
                al[mt][0] = *(const uint32_t*)&Pl[r];
                al[mt][1] = *(const uint32_t*)&Pl[r + 8 * PST];
                al[mt][2] = *(const uint32_t*)&Pl[r + 8];
                al[mt][3] = *(const uint32_t*)&Pl[r + 8 * PST + 8];
            }
            uint32_t bh[4][2], bl[4][2];
            #pragma unroll
            for (int nt = 0; nt < 4; nt++) {
                int r = (wn * 32 + nt * 8 + g) * PST + ks + 2 * tq;
                bh[nt][0] = *(const uint32_t*)&Vh[r];
                bh[nt][1] = *(const uint32_t*)&Vh[r + 8];
                bl[nt][0] = *(const uint32_t*)&Vl[r];
                bl[nt][1] = *(const uint32_t*)&Vl[r + 8];
            }
            #pragma unroll
            for (int mt = 0; mt < 2; mt++)
                #pragma unroll
                for (int nt = 0; nt < 4; nt++) {
                    MMA_OP(acc[mt][nt], ah[mt], bh[nt]);
                    MMA_OP(acc[mt][nt], ah[mt], bl[nt]);
                    MMA_OP(acc[mt][nt], al[mt], bh[nt]);
                }
        }
    };

    LOADG(0);
    STORES(0);
    __syncthreads();
    const int NKT = SEQ / 32;
    for (int kt_i = 0; kt_i < NKT; kt_i++) {
        if (kt_i + 1 < NKT) LOADG((kt_i + 1) * 32);
        COMPUTE(kt_i & 1);
        if (kt_i + 1 < NKT) STORES((kt_i & 1) ^ 1);
        __syncthreads();
    }

    #pragma unroll
    for (int mt = 0; mt < 2; mt++)
        #pragma unroll
        for (int nt = 0; nt < 4; nt++) {
            int qq = q0 + wm * 32 + mt * 16 + g;
            int dd = wn * 32 + nt * 8 + 2 * tq;
            *(float2*)&out[(b * SEQ + qq) * DMODEL + dd] =
                make_float2(acc[mt][nt][0], acc[mt][nt][1]);
            *(float2*)&out[(b * SEQ + qq + 8) * DMODEL + dd] =
                make_float2(acc[mt][nt][2], acc[mt][nt][3]);
        }
}

// ============================================================
extern "C" void kernel_launch(void* const* d_in, const int* in_sizes, int n_in,
                              void* d_out, int out_size)
{
    const float* queries = (const float*)d_in[0];
    const float* keys    = (const float*)d_in[1];
    const float* values  = (const float*)d_in[2];
    const int*   vlens   = (const int*)  d_in[3];
    const float* Wql     = (const float*)d_in[4];
    const float* bql     = (const float*)d_in[5];
    const float* Wkl     = (const float*)d_in[6];
    const float* bkl     = (const float*)d_in[7];
    const float* Wqh     = (const float*)d_in[8];
    const float* bqh     = (const float*)d_in[9];
    const float* Wkh     = (const float*)d_in[10];
    const float* bkh     = (const float*)d_in[11];
    float* out = (float*)d_out;

    static bool attr_set = false;
    if (!attr_set) {
        cudaFuncSetAttribute(out_gemm_mma,
                             cudaFuncAttributeMaxDynamicSharedMemorySize, MMA_SMEM);
        attr_set = true;
    }

    zero_kernel<<<BATCH * SEQ / 256, 256>>>();
    proj_kernel<<<BATCH * SEQ, 64>>>(queries, keys, Wql, bql, Wkl, bkl,
                                     Wqh, bqh, Wkh, bkh);
    scores_kernel<<<dim3(SEQ / 128, SEQ / 64, BATCH), 256>>>(vlens);
    topk_kernel<<<BATCH * SEQ / 8, 256>>>();
    vconv_kernel<<<dim3(SEQ / 32, BATCH), 256>>>(values);
    out_gemm_mma<<<dim3(SEQ / 64, BATCH), 256, MMA_SMEM>>>(out);
}

// round 13
// speedup vs baseline: 2.1611x; 1.0156x over previous
#include <cuda_runtime.h>
#include <cuda_bf16.h>
#include <cstdint>
#include <cfloat>

#define BATCH 4
#define SEQ   2048
#define DMODEL 128
#define DLOW  16
#define NEGV  (-1e9f)
#define SCALE 0.25f
#define NQB   32

// ---- scratch (static __device__, no allocations) ----
__device__ float g_S[BATCH * SEQ * SEQ];          // 64 MB: exp(corrected scores)
__device__ float g_qlow[BATCH * SEQ * DLOW];
__device__ float g_klowT[BATCH * DLOW * SEQ];
__device__ float g_c[BATCH * SEQ];                // exp(correction score)
__device__ float g_part[NQB][BATCH * SEQ];
__device__ float g_Zadj[BATCH * SEQ];
__device__ float g_cmax[BATCH * SEQ * 16];        // per-row per-128-chunk maxima
__device__ __nv_bfloat16 g_VhT[BATCH * DMODEL * SEQ];   // (V*w)^T hi, [b][d][k]
__device__ __nv_bfloat16 g_VlT[BATCH * DMODEL * SEQ];   // (V*w)^T lo

// ============================================================
// K1: projections. One block (64 threads) per (b, position).
// Also zeroes g_Zadj (fused, drops a launch).
// ============================================================
__global__ void proj_kernel(const float* __restrict__ q, const float* __restrict__ k,
                            const float* __restrict__ Wql, const float* __restrict__ bql,
                            const float* __restrict__ Wkl, const float* __restrict__ bkl,
                            const float* __restrict__ Wqh, const float* __restrict__ bqh,
                            const float* __restrict__ Wkh, const float* __restrict__ bkh)
{
    int p = blockIdx.x;
    int b = p >> 11, i = p & (SEQ - 1);
    __shared__ float qs[DMODEL], ks[DMODEL];
    __shared__ float qh[DLOW], kh[DLOW];
    int t = threadIdx.x;
    if (t == 1) g_Zadj[p] = 0.f;
    {
        float2 qv = *(const float2*)&q[p * DMODEL + t * 2];
        qs[t * 2] = qv.x; qs[t * 2 + 1] = qv.y;
        float2 kv = *(const float2*)&k[p * DMODEL + t * 2];
        ks[t * 2] = kv.x; ks[t * 2 + 1] = kv.y;
    }
    __syncthreads();
    int j = t & 15;
    int which = t >> 4;
    const float* W; const float* bias; const float* src;
    if (which == 0)      { W = Wql; bias = bql; src = qs; }
    else if (which == 1) { W = Wkl; bias = bkl; src = ks; }
    else if (which == 2) { W = Wqh; bias = bqh; src = qs; }
    else                 { W = Wkh; bias = bkh; src = ks; }
    float acc = bias[j];
    #pragma unroll 16
    for (int d0 = 0; d0 < DMODEL; d0++)
        acc = fmaf(src[d0], W[d0 * DLOW + j], acc);
    if (which == 0)      g_qlow[p * DLOW + j] = acc;
    else if (which == 1) g_klowT[(b * DLOW + j) * SEQ + i] = acc;
    else if (which == 2) qh[j] = acc;
    else                 kh[j] = acc;
    __syncthreads();
    if (t == 0) {
        float c = 0.f;
        #pragma unroll
        for (int jj = 0; jj < DLOW; jj++) c = fmaf(qh[jj], kh[jj], c);
        g_c[p] = __expf(c * SCALE);
    }
}

// ============================================================
// K2a: exp(masked low-rank scores) + column partial sums
//      + per-row chunk maxima (for single-pass top-k threshold).
// ============================================================
__global__ void scores_kernel(const int* __restrict__ valid_lens)
{
    int b  = blockIdx.z;
    int q0 = blockIdx.y * 64;
    int k0 = blockIdx.x * 128;
    __shared__ float qT[DLOW][64];
    __shared__ float kS[DLOW][128];
    __shared__ float redsm[8][128];
    int t = threadIdx.x;
    {
        int row = t >> 2, j0 = (t & 3) * 4;
        const float4 v = *(const float4*)&g_qlow[(b * SEQ + q0 + row) * DLOW + j0];
        qT[j0 + 0][row] = v.x; qT[j0 + 1][row] = v.y;
        qT[j0 + 2][row] = v.z; qT[j0 + 3][row] = v.w;
    }
    {
        int row = t >> 5, c0 = (t & 31) * 4;
        #pragma unroll
        for (int r = 0; r < DLOW; r += 8)
            *(float4*)&kS[row + r][c0] =
                *(const float4*)&g_klowT[(b * DLOW + row + r) * SEQ + k0 + c0];
    }
    __syncthreads();
    int tx = t & 31, ty = t >> 5;
    int m0 = ty * 8, n0 = tx * 4;
    float acc[8][4];
    #pragma unroll
    for (int i = 0; i < 8; i++)
        #pragma unroll
        for (int jj = 0; jj < 4; jj++) acc[i][jj] = 0.f;
    #pragma unroll
    for (int j = 0; j < DLOW; j++) {
        float a[8];
        *(float4*)&a[0] = *(const float4*)&qT[j][m0];
        *(float4*)&a[4] = *(const float4*)&qT[j][m0 + 4];
        float4 bv = *(const float4*)&kS[j][n0];
        #pragma unroll
        for (int i = 0; i < 8; i++) {
            acc[i][0] = fmaf(a[i], bv.x, acc[i][0]);
            acc[i][1] = fmaf(a[i], bv.y, acc[i][1]);
            acc[i][2] = fmaf(a[i], bv.z, acc[i][2]);
            acc[i][3] = fmaf(a[i], bv.w, acc[i][3]);
        }
    }
    int vl[4];
    #pragma unroll
    for (int jj = 0; jj < 4; jj++) {
        int v = valid_lens[b * SEQ + k0 + n0 + jj];
        vl[jj] = min(max(v, 0), SEQ - 1);
    }
    float cs[4] = {0.f, 0.f, 0.f, 0.f};
    float rmax[8];
    #pragma unroll
    for (int i = 0; i < 8; i++) {
        int qrow = q0 + m0 + i;
        float4 o; float* po = (float*)&o;
        float rm = -FLT_MAX;
        #pragma unroll
        for (int jj = 0; jj < 4; jj++) {
            float v = acc[i][jj] * SCALE;
            if (vl[jj] == qrow) v += NEGV;
            float e = __expf(v);
            po[jj] = e;
            cs[jj] += e;
            rm = fmaxf(rm, e);
        }
        rmax[i] = rm;
        *(float4*)&g_S[(b * SEQ + qrow) * SEQ + k0 + n0] = o;
    }
    #pragma unroll
    for (int i = 0; i < 8; i++) {
        float rm = rmax[i];
        #pragma unroll
        for (int off = 16; off > 0; off >>= 1)
            rm = fmaxf(rm, __shfl_xor_sync(0xffffffffu, rm, off));
        if (tx == 0)
            g_cmax[(b * SEQ + q0 + m0 + i) * 16 + blockIdx.x] = rm;
    }
    #pragma unroll
    for (int jj = 0; jj < 4; jj++) redsm[ty][n0 + jj] = cs[jj];
    __syncthreads();
    if (t < 128) {
        float s = 0.f;
        #pragma unroll
        for (int r = 0; r < 8; r++) s += redsm[r][t];
        g_part[blockIdx.y][b * SEQ + k0 + t] = s;
    }
}

// ============================================================
// K2b: warp-per-row exact threshold top-8 with chunk skipping.
// T = 8th largest of the 16 chunk maxima. Chunks with cmax < T
// cannot contain a candidate -> skip (~half the row). Surviving
// chunks use a vector-max pretest per float4 before element checks.
// ============================================================
__global__ void __launch_bounds__(256) topk_kernel()
{
    __shared__ float cV[8][64];
    __shared__ int   cI[8][64];
    __shared__ int   cnt[8];
    int t = threadIdx.x, lane = t & 31, w = t >> 5;
    int row = blockIdx.x * 8 + w;                 // 0..8191
    int b = row >> 11;
    float* Srow = &g_S[row * SEQ];

    // threshold from precomputed chunk maxima
    float cm0 = (lane < 16) ? g_cmax[row * 16 + lane] : -FLT_MAX;
    float a = cm0, T = cm0;
    #pragma unroll
    for (int it = 0; it < 8; it++) {
        float m = a;
        #pragma unroll
        for (int off = 16; off > 0; off >>= 1)
            m = fmaxf(m, __shfl_xor_sync(0xffffffffu, m, off));
        T = m;
        unsigned ba = __ballot_sync(0xffffffffu, a == m);
        if (lane == (int)(__ffs(ba) - 1)) a = -FLT_MAX;
    }

    // chunks that can contain candidates
    unsigned chunkmask = __ballot_sync(0xffffffffu, cm0 >= T) & 0xffffu;

    if (lane == 0) cnt[w] = 0;
    __syncwarp();
    unsigned mrem = chunkmask;
    while (mrem) {
        int c = __ffs(mrem) - 1;
        mrem &= mrem - 1;
        int off = c * 128 + lane * 4;
        float4 x = *(const float4*)&Srow[off];
        float m4 = fmaxf(fmaxf(x.x, x.y), fmaxf(x.z, x.w));
        if (m4 >= T) {
            const float* xv = (const float*)&x;
            #pragma unroll
            for (int jj = 0; jj < 4; jj++) {
                if (xv[jj] >= T) {
                    int p = atomicAdd(&cnt[w], 1);
                    if (p < 64) { cV[w][p] = xv[jj]; cI[w][p] = off + jj; }
                }
            }
        }
    }
    __syncwarp();
    int nc = cnt[w];

    int   chI[8];
    float chV[8];

    if (nc <= 64) {
        #pragma unroll 1
        for (int it = 0; it < 8; it++) {
            float bv = -FLT_MAX; int bi = 0x7fffffff;
            for (int p = lane; p < nc; p += 32) {
                float cv = cV[w][p]; int ci = cI[w][p];
                if (cv > bv || (cv == bv && ci < bi)) { bv = cv; bi = ci; }
            }
            #pragma unroll
            for (int off = 16; off > 0; off >>= 1) {
                float ov = __shfl_xor_sync(0xffffffffu, bv, off);
                int   oi = __shfl_xor_sync(0xffffffffu, bi, off);
                if (ov > bv || (ov == bv && oi < bi)) { bv = ov; bi = oi; }
            }
            for (int p = lane; p < nc; p += 32)
                if (cI[w][p] == bi) cV[w][p] = -FLT_MAX;
            chI[it] = bi; chV[it] = bv;
        }
    } else {
        // exact slow path: iterative argmax with chosen-exclusion (global rescan)
        #pragma unroll 1
        for (int it = 0; it < 8; it++) {
            float bv = -FLT_MAX; int bi = 0x7fffffff;
            for (int p = lane; p < SEQ; p += 32) {
                bool skip = false;
                #pragma unroll 8
                for (int x = 0; x < 8; x++)
                    if (x < it && chI[x] == p) skip = true;
                if (skip) continue;
                float cv = Srow[p];
                if (cv > bv || (cv == bv && p < bi)) { bv = cv; bi = p; }
            }
            #pragma unroll
            for (int off = 16; off > 0; off >>= 1) {
                float ov = __shfl_xor_sync(0xffffffffu, bv, off);
                int   oi = __shfl_xor_sync(0xffffffffu, bi, off);
                if (ov > bv || (ov == bv && oi < bi)) { bv = ov; bi = oi; }
            }
            chI[it] = bi; chV[it] = bv;
        }
    }

    if (lane == 0) {
        #pragma unroll
        for (int it = 0; it < 8; it++) {
            int bi = chI[it];
            float ec = g_c[b * SEQ + bi];
            Srow[bi] = ec;
            atomicAdd(&g_Zadj[b * SEQ + bi], ec - chV[it]);
        }
    }
}

// ============================================================
// K3: (V*w)^T split into bf16 hi/lo, [b][d][k]; finalize (w = 1/Z) fused.
// ============================================================
__global__ void vconv_kernel(const float* __restrict__ V)
{
    int b = blockIdx.y, k0 = blockIdx.x * 32;
    __shared__ float vs[32][129];
    __shared__ float wsh[32];
    int t = threadIdx.x;
    if (t < 32) {
        int idx = b * SEQ + k0 + t;
        float z = g_Zadj[idx];
        #pragma unroll
        for (int s = 0; s < NQB; s++) z += g_part[s][idx];
        wsh[t] = 1.0f / z;
    }
    __syncthreads();
    {
        int r = t >> 3, c0 = (t & 7) * 16;
        float wk = wsh[r];
        #pragma unroll
        for (int qd = 0; qd < 4; qd++) {
            float4 vv = *(const float4*)&V[(b * SEQ + k0 + r) * DMODEL + c0 + qd * 4];
            vs[r][c0 + qd * 4 + 0] = vv.x * wk;
            vs[r][c0 + qd * 4 + 1] = vv.y * wk;
            vs[r][c0 + qd * 4 + 2] = vv.z * wk;
            vs[r][c0 + qd * 4 + 3] = vv.w * wk;
        }
    }
    __syncthreads();
    int d = t >> 1, kh = (t & 1) * 16;
    uint4 hq[2], lq[2];
    __nv_bfloat162* hp = (__nv_bfloat162*)hq;
    __nv_bfloat162* lp = (__nv_bfloat162*)lq;
    #pragma unroll
    for (int i = 0; i < 8; i++) {
        float x0 = vs[kh + 2 * i][d], x1 = vs[kh + 2 * i + 1][d];
        __nv_bfloat16 h0 = __float2bfloat16(x0), h1 = __float2bfloat16(x1);
        hp[i] = __halves2bfloat162(h0, h1);
        lp[i] = __halves2bfloat162(__float2bfloat16(x0 - __bfloat162float(h0)),
                                   __float2bfloat16(x1 - __bfloat162float(h1)));
    }
    __nv_bfloat16* dsth = &g_VhT[(b * DMODEL + d) * SEQ + k0 + kh];
    *(uint4*)dsth = hq[0];
    *((uint4*)dsth + 1) = hq[1];
    __nv_bfloat16* dstl = &g_VlT[(b * DMODEL + d) * SEQ + k0 + kh];
    *(uint4*)dstl = lq[0];
    *((uint4*)dstl + 1) = lq[1];
}

// ============================================================
// K4: tensor-core output GEMM with split-bf16 compensation.
// ============================================================
#define PST   40
#define P_SZ  (64 * PST)
#define V_SZ  (128 * PST)
#define BUFE  (2 * P_SZ + 2 * V_SZ)
#define MMA_SMEM (2 * BUFE * 2)

#define MMA_OP(c, a, bb) \
    asm volatile("mma.sync.aligned.m16n8k16.row.col.f32.bf16.bf16.f32 " \
        "{%0,%1,%2,%3}, {%4,%5,%6,%7}, {%8,%9}, {%0,%1,%2,%3};" \
        : "+f"((c)[0]), "+f"((c)[1]), "+f"((c)[2]), "+f"((c)[3]) \
        : "r"((a)[0]), "r"((a)[1]), "r"((a)[2]), "r"((a)[3]), \
          "r"((bb)[0]), "r"((bb)[1]))

__global__ void __launch_bounds__(256) out_gemm_mma(float* __restrict__ out)
{
    extern __shared__ __nv_bfloat16 smb[];
    int b = blockIdx.y, q0 = blockIdx.x * 64;
    int t = threadIdx.x, lane = t & 31, w = t >> 5;
    int g = lane >> 2, tq = lane & 3;
    int wm = w >> 2, wn = w & 3;

    const float* Sbase = &g_S[(b * SEQ + q0) * SEQ];
    const __nv_bfloat16* VhB = &g_VhT[b * DMODEL * SEQ];
    const __nv_bfloat16* VlB = &g_VlT[b * DMODEL * SEQ];

    int s_q = t >> 2, s_k = (t & 3) * 8;
    int v_d = t >> 1, v_k = (t & 1) * 16;

    float acc[2][4][4];
    #pragma unroll
    for (int mt = 0; mt < 2; mt++)
        #pragma unroll
        for (int nt = 0; nt < 4; nt++)
            #pragma unroll
            for (int x = 0; x < 4; x++) acc[mt][nt][x] = 0.f;

    float4 sP[2]; uint4 sVh[2], sVl[2];

    auto LOADG = [&](int kt) {
        sP[0] = *(const float4*)&Sbase[s_q * SEQ + kt + s_k];
        sP[1] = *(const float4*)&Sbase[s_q * SEQ + kt + s_k + 4];
        const uint4* ph = (const uint4*)&VhB[v_d * SEQ + kt + v_k];
        sVh[0] = ph[0]; sVh[1] = ph[1];
        const uint4* pl = (const uint4*)&VlB[v_d * SEQ + kt + v_k];
        sVl[0] = pl[0]; sVl[1] = pl[1];
    };
    auto STORES = [&](int buf) {
        __nv_bfloat16* Ph = smb + buf * BUFE;
        __nv_bfloat16* Pl = Ph + P_SZ;
        __nv_bfloat16* Vh = Ph + 2 * P_SZ;
        __nv_bfloat16* Vl = Vh + V_SZ;
        float f[8];
        *(float4*)&f[0] = sP[0]; *(float4*)&f[4] = sP[1];
        uint4 hq, lq;
        __nv_bfloat162* hp = (__nv_bfloat162*)&hq;
        __nv_bfloat162* lp = (__nv_bfloat162*)&lq;
        #pragma unroll
        for (int i = 0; i < 4; i++) {
            __nv_bfloat16 h0 = __float2bfloat16(f[2 * i]);
            __nv_bfloat16 h1 = __float2bfloat16(f[2 * i + 1]);
            hp[i] = __halves2bfloat162(h0, h1);
            lp[i] = __halves2bfloat162(
                __float2bfloat16(f[2 * i] - __bfloat162float(h0)),
                __float2bfloat16(f[2 * i + 1] - __bfloat162float(h1)));
        }
        *(uint4*)&Ph[s_q * PST + s_k] = hq;
        *(uint4*)&Pl[s_q * PST + s_k] = lq;
        *(uint4*)&Vh[v_d * PST + v_k]     = sVh[0];
        *(uint4*)&Vh[v_d * PST + v_k + 8] = sVh[1];
        *(uint4*)&Vl[v_d * PST + v_k]     = sVl[0];
        *(uint4*)&Vl[v_d * PST + v_k + 8] = sVl[1];
    };
    auto COMPUTE = [&](int buf) {
        const __nv_bfloat16* Ph = smb + buf * BUFE;
        const __nv_bfloat16* Pl = Ph + P_SZ;
        const __nv_bfloat16* Vh = Ph + 2 * P_SZ;
        const __nv_bfloat16* Vl = Vh + V_SZ;
        #pragma unroll
        for (int ks = 0; ks < 32; ks += 16) {
            uint32_t ah[2][4], al[2][4];
            #pragma unroll
            for (int mt = 0; mt < 2; mt++) {
                int r = (wm * 32 + mt * 16 + g) * PST + ks + 2 * tq;
                ah[mt][0] = *(const uint32_t*)&Ph[r];
                ah[mt][1] = *(const uint32_t*)&Ph[r + 8 * PST];
                ah[mt][2] = *(const uint32_t*)&Ph[r + 8];
                ah[mt][3] = *(const uint32_t*)&Ph[r + 8 * PST + 8];
                al[mt][0] = *(const uint32_t*)&Pl[r];
                al[mt][1] = *(const uint32_t*)&Pl[r + 8 * PST];
                al[mt][2] = *(const uint32_t*)&Pl[r + 8];
                al[mt][3] = *(const uint32_t*)&Pl[r + 8 * PST + 8];
            }
            uint32_t bh[4][2], bl[4][2];
            #pragma unroll
            for (int nt = 0; nt < 4; nt++) {
                int r = (wn * 32 + nt * 8 + g) * PST + ks + 2 * tq;
                bh[nt][0] = *(const uint32_t*)&Vh[r];
                bh[nt][1] = *(const uint32_t*)&Vh[r + 8];
                bl[nt][0] = *(const uint32_t*)&Vl[r];
                bl[nt][1] = *(const uint32_t*)&Vl[r + 8];
            }
            #pragma unroll
            for (int mt = 0; mt < 2; mt++)
                #pragma unroll
                for (int nt = 0; nt < 4; nt++) {
                    MMA_OP(acc[mt][nt], ah[mt], bh[nt]);
                    MMA_OP(acc[mt][nt], ah[mt], bl[nt]);
                    MMA_OP(acc[mt][nt], al[mt], bh[nt]);
                }
        }
    };

    LOADG(0);
    STORES(0);
    __syncthreads();
    const int NKT = SEQ / 32;
    for (int kt_i = 0; kt_i < NKT; kt_i++) {
        if (kt_i + 1 < NKT) LOADG((kt_i + 1) * 32);
        COMPUTE(kt_i & 1);
        if (kt_i + 1 < NKT) STORES((kt_i & 1) ^ 1);
        __syncthreads();
    }

    #pragma unroll
    for (int mt = 0; mt < 2; mt++)
        #pragma unroll
        for (int nt = 0; nt < 4; nt++) {
            int qq = q0 + wm * 32 + mt * 16 + g;
            int dd = wn * 32 + nt * 8 + 2 * tq;
            *(float2*)&out[(b * SEQ + qq) * DMODEL + dd] =
                make_float2(acc[mt][nt][0], acc[mt][nt][1]);
            *(float2*)&out[(b * SEQ + qq + 8) * DMODEL + dd] =
                make_float2(acc[mt][nt][2], acc[mt][nt][3]);
        }
}

// ============================================================
extern "C" void kernel_launch(void* const* d_in, const int* in_sizes, int n_in,
                              void* d_out, int out_size)
{
    const float* queries = (const float*)d_in[0];
    const float* keys    = (const float*)d_in[1];
    const float* values  = (const float*)d_in[2];
    const int*   vlens   = (const int*)  d_in[3];
    const float* Wql     = (const float*)d_in[4];
    const float* bql     = (const float*)d_in[5];
    const float* Wkl     = (const float*)d_in[6];
    const float* bkl     = (const float*)d_in[7];
    const float* Wqh     = (const float*)d_in[8];
    const float* bqh     = (const float*)d_in[9];
    const float* Wkh     = (const float*)d_in[10];
    const float* bkh     = (const float*)d_in[11];
    float* out = (float*)d_out;

    static bool attr_set = false;
    if (!attr_set) {
        cudaFuncSetAttribute(out_gemm_mma,
                             cudaFuncAttributeMaxDynamicSharedMemorySize, MMA_SMEM);
        attr_set = true;
    }

    proj_kernel<<<BATCH * SEQ, 64>>>(queries, keys, Wql, bql, Wkl, bkl,
                                     Wqh, bqh, Wkh, bkh);
    scores_kernel<<<dim3(SEQ / 128, SEQ / 64, BATCH), 256>>>(vlens);
    topk_kernel<<<BATCH * SEQ / 8, 256>>>();
    vconv_kernel<<<dim3(SEQ / 32, BATCH), 256>>>(values);
    out_gemm_mma<<<dim3(SEQ / 64, BATCH), 256, MMA_SMEM>>>(out);
}